// round 10
// baseline (speedup 1.0000x reference)
#include <cuda_runtime.h>
#include <math.h>
#include <stdint.h>

#define S_   1024
#define H_   1024
#define NH_  16
#define KVH_ 8
#define HD_  64
#define E_   64
#define TK_  8
#define I_   3072
#define C_   512
#define MAXPAIRS_ (S_*TK_)

// ---------------- scratch ----------------
__device__ float g_xln [S_*H_];
__device__ float g_qkv [S_*2048];
__device__ float g_q   [NH_*S_*HD_];
__device__ float g_k   [KVH_*S_*HD_];
__device__ float g_v   [KVH_*S_*HD_];
__device__ float g_attn[S_*H_];
__device__ float g_h1  [S_*H_];
__device__ float g_x2  [S_*H_];
__device__ float g_gu  [(size_t)MAXPAIRS_*2*I_];
__device__ float g_act [(size_t)MAXPAIRS_*I_];
__device__ float g_sh  [S_*H_];
__device__ float g_lg  [S_*E_];
__device__ float g_w8  [S_*TK_];
__device__ int   g_idx8[S_*TK_];
__device__ int   g_ppos[S_*TK_];
__device__ int   g_etok[E_*C_];
__device__ int   g_ecnt[E_];
__device__ int   g_eoff[E_+1];
__device__ float g_ye  [(size_t)MAXPAIRS_*H_];

// ---------------- helpers ----------------
__device__ __forceinline__ uint32_t smem_u32(const void* p){
    uint32_t a;
    asm("{ .reg .u64 t; cvta.to.shared.u64 t, %1; cvt.u32.u64 %0, t; }" : "=r"(a) : "l"(p));
    return a;
}
__device__ __forceinline__ void mma_tf32(float* c, const uint32_t* a, const uint32_t* b){
    asm volatile("mma.sync.aligned.m16n8k8.row.col.f32.tf32.tf32.f32 "
        "{%0,%1,%2,%3}, {%4,%5,%6,%7}, {%8,%9}, {%0,%1,%2,%3};"
        : "+f"(c[0]), "+f"(c[1]), "+f"(c[2]), "+f"(c[3])
        : "r"(a[0]), "r"(a[1]), "r"(a[2]), "r"(a[3]), "r"(b[0]), "r"(b[1]));
}
__device__ __forceinline__ void cpa16(uint32_t sm, const void* g, int sz){
    asm volatile("cp.async.cg.shared.global [%0], [%1], 16, %2;"
                 :: "r"(sm), "l"(g), "r"(sz) : "memory");
}
#define CP_COMMIT() asm volatile("cp.async.commit_group;" ::: "memory")
#define CP_WAIT2()  asm volatile("cp.async.wait_group 2;" ::: "memory")
#define CP_WAIT1()  asm volatile("cp.async.wait_group 1;" ::: "memory")
#define CP_WAIT0()  asm volatile("cp.async.wait_group 0;" ::: "memory")

// smem per stage (floats): As[128][20] + Bs[16][136]
#define AS_PITCH 20
#define BS_PITCH 136
#define ASZ (128*AS_PITCH)           // 2560
#define BSZ (16*BS_PITCH)            // 2176
#define STG_FLOATS (ASZ+BSZ)         // 4736
#define NSTG 4
#define SMEM_BYTES (NSTG*STG_FLOATS*4)  // 75776

extern __shared__ float dsmf[];

// ---------------- tf32 GEMM: 128x128 tile, 128 thr (4 warps, 64x64 each), 4-stage cp.async ----------------
__device__ __forceinline__ void tgemm_core(
    const float* __restrict__ A, int lda, const int* __restrict__ gidx,
    const float* __restrict__ B, int ldb,
    float* __restrict__ Cc, int ldc, const float* __restrict__ res,
    int Mv, int Kd, int m0, int n0)
{
    int tid = threadIdx.x, lane = tid & 31, wid = tid >> 5;
    int wm = wid & 1, wn = wid >> 1;          // 2x2 warp grid
    int gq = lane >> 2, lq = lane & 3;
    uint32_t smb = smem_u32(dsmf);

    // A loader: rows tid>>1 and +64, col half (tid&1)*8
    int ar = tid >> 1, ac = (tid & 1) * 8;
    int gr0 = m0 + ar, gr1 = m0 + ar + 64;
    int rid0 = (gr0 < Mv) ? (gidx ? gidx[gr0] : gr0) : -1;
    int rid1 = (gr1 < Mv) ? (gidx ? gidx[gr1] : gr1) : -1;
    const float* A0 = (rid0 >= 0) ? (A + (size_t)rid0*lda + ac) : A;
    const float* A1 = (rid1 >= 0) ? (A + (size_t)rid1*lda + ac) : A;
    int sz0 = (rid0 >= 0) ? 16 : 0, sz1 = (rid1 >= 0) ? 16 : 0;
    // B loader: row tid>>3 (0..15), 16 consecutive cols (tid&7)*16
    int br = tid >> 3, bc = (tid & 7) * 16;
    const float* Bp = B + (size_t)br*ldb + n0 + bc;

    uint32_t aD0 = smb + (uint32_t)(ar*AS_PITCH + ac)*4;
    uint32_t aD1 = smb + (uint32_t)((ar+64)*AS_PITCH + ac)*4;
    uint32_t bD  = smb + (uint32_t)(ASZ + br*BS_PITCH + bc)*4;
    const uint32_t STRB = STG_FLOATS*4;

    int T = Kd >> 4;

    float acc[4][8][4];
    #pragma unroll
    for (int i=0;i<4;i++)
        #pragma unroll
        for (int j=0;j<8;j++)
            #pragma unroll
            for (int q=0;q<4;q++) acc[i][j][q]=0.f;

    auto issue = [&](int t){
        uint32_t so = (uint32_t)(t & 3) * STRB;
        int k0 = t << 4;
        cpa16(aD0 + so,      A0 + k0,     sz0);
        cpa16(aD0 + so + 16, A0 + k0 + 4, sz0);
        cpa16(aD1 + so,      A1 + k0,     sz1);
        cpa16(aD1 + so + 16, A1 + k0 + 4, sz1);
        const float* bs = Bp + (size_t)k0*ldb;
        cpa16(bD + so,      bs,      16);
        cpa16(bD + so + 16, bs + 4,  16);
        cpa16(bD + so + 32, bs + 8,  16);
        cpa16(bD + so + 48, bs + 12, 16);
        CP_COMMIT();
    };

    #pragma unroll
    for (int s=0; s<NSTG-1; s++){
        if (s < T) issue(s); else CP_COMMIT();
    }

    for (int t=0; t<T; t++){
        CP_WAIT2();
        __syncthreads();
        if (t + NSTG-1 < T) issue(t + NSTG-1); else CP_COMMIT();

        const uint32_t* As = (const uint32_t*)(dsmf + (size_t)(t&3)*STG_FLOATS);
        const uint32_t* Bs = As + ASZ;
        #pragma unroll
        for (int kk=0; kk<16; kk+=8){
            uint32_t a[4][4], b[8][2];
            #pragma unroll
            for (int i=0;i<4;i++){
                int rb = wm*64 + i*16 + gq;
                int c  = kk + lq;
                a[i][0] = As[rb*AS_PITCH + c];
                a[i][1] = As[(rb+8)*AS_PITCH + c];
                a[i][2] = As[rb*AS_PITCH + c + 4];
                a[i][3] = As[(rb+8)*AS_PITCH + c + 4];
            }
            #pragma unroll
            for (int j=0;j<8;j++){
                int col = wn*64 + j*8 + gq;
                int row = kk + lq;
                b[j][0] = Bs[row*BS_PITCH + col];
                b[j][1] = Bs[(row+4)*BS_PITCH + col];
            }
            #pragma unroll
            for (int i=0;i<4;i++)
                #pragma unroll
                for (int j=0;j<8;j++)
                    mma_tf32(acc[i][j], a[i], b[j]);
        }
    }

    #pragma unroll
    for (int i=0;i<4;i++){
        #pragma unroll
        for (int h=0;h<2;h++){
            int row = m0 + wm*64 + i*16 + gq + h*8;
            if (row < Mv){
                float* crow = Cc + (size_t)row*ldc;
                const float* rrow = res ? (res + (size_t)row*ldc) : nullptr;
                #pragma unroll
                for (int j=0;j<8;j++){
                    int cix = n0 + wn*64 + j*8 + lq*2;
                    float2 v = make_float2(acc[i][j][h*2], acc[i][j][h*2+1]);
                    if (rrow){
                        float2 rv = *(const float2*)(rrow + cix);
                        v.x += rv.x; v.y += rv.y;
                    }
                    *(float2*)(crow + cix) = v;
                }
            }
        }
    }
}

__global__ void __launch_bounds__(128,2)
k_tgemm(const float* A, int lda, const float* B, int ldb,
        float* Cc, int ldc, const float* res, int Mv, int Kd){
    tgemm_core(A, lda, nullptr, B, ldb, Cc, ldc, res, Mv, Kd,
               blockIdx.y*128, blockIdx.x*128);
}

__global__ void __launch_bounds__(128,2)
k_tgemm_egu(const float* X, const float* Wgu){
    int e = blockIdx.z, cnt = g_ecnt[e], m0 = blockIdx.y*128;
    if (m0 >= cnt) return;
    tgemm_core(X, H_, &g_etok[e*C_], Wgu + (size_t)e*H_*2*I_, 2*I_,
               &g_gu[(size_t)g_eoff[e]*2*I_], 2*I_, nullptr, cnt, H_,
               m0, blockIdx.x*128);
}

__global__ void __launch_bounds__(128,2)
k_tgemm_edn(const float* Wd){
    int e = blockIdx.z, cnt = g_ecnt[e], m0 = blockIdx.y*128;
    if (m0 >= cnt) return;
    int off = g_eoff[e];
    tgemm_core(&g_act[(size_t)off*I_], I_, nullptr, Wd + (size_t)e*I_*H_, H_,
               &g_ye[(size_t)off*H_], H_, nullptr, cnt, I_,
               m0, blockIdx.x*128);
}

// ---------------- elementwise / routing ----------------
__global__ void k_rmsnorm(const float* __restrict__ x, const float* __restrict__ w,
                          float* __restrict__ y){
    int row = blockIdx.x, tid = threadIdx.x;
    float4 xv = ((const float4*)(x + (size_t)row*H_))[tid];
    float ss = xv.x*xv.x + xv.y*xv.y + xv.z*xv.z + xv.w*xv.w;
    #pragma unroll
    for (int m=16;m;m>>=1) ss += __shfl_xor_sync(0xffffffffu, ss, m);
    __shared__ float wsum[8];
    if ((tid&31)==0) wsum[tid>>5]=ss;
    __syncthreads();
    if (tid<8){
        float v=wsum[tid];
        #pragma unroll
        for (int m=4;m;m>>=1) v+=__shfl_xor_sync(0xffu,v,m);
        if (tid==0) wsum[0]=v;
    }
    __syncthreads();
    float inv = rsqrtf(wsum[0]*(1.0f/H_) + 1e-6f);
    float4 wv = ((const float4*)w)[tid];
    ((float4*)(y + (size_t)row*H_))[tid] =
        make_float4(wv.x*xv.x*inv, wv.y*xv.y*inv, wv.z*xv.z*inv, wv.w*xv.w*inv);
}

__global__ void k_rope(const float* __restrict__ qkv, const float* __restrict__ cb,
                       const float* __restrict__ sb, const float* __restrict__ qw,
                       const float* __restrict__ kw){
    int s = blockIdx.x, y = blockIdx.y, lane = threadIdx.x;
    const float* base; float* outp; const float* w;
    if (y < NH_){
        int kvh = y>>1, g = y&1;
        base = qkv + (size_t)s*2048 + kvh*256 + g*64;
        outp = &g_q[((size_t)y*S_ + s)*HD_];
        w = qw;
    } else {
        int kvh = y - NH_;
        base = qkv + (size_t)s*2048 + kvh*256 + 128;
        outp = &g_k[((size_t)kvh*S_ + s)*HD_];
        w = kw;
        float* vo = &g_v[((size_t)kvh*S_ + s)*HD_];
        vo[lane] = base[64+lane]; vo[lane+32] = base[96+lane];
    }
    float x0 = base[lane], x1 = base[lane+32];
    float r0 = x0*cb[s*HD_+lane]    - x1*sb[s*HD_+lane];
    float r1 = x1*cb[s*HD_+32+lane] + x0*sb[s*HD_+32+lane];
    float ss = r0*r0 + r1*r1;
    #pragma unroll
    for (int m=16;m;m>>=1) ss += __shfl_xor_sync(0xffffffffu, ss, m);
    float inv = rsqrtf(ss*(1.f/HD_) + 1e-6f);
    outp[lane] = w[lane]*r0*inv;
    outp[lane+32] = w[lane+32]*r1*inv;
}

// ---------------- attention: BQ=32, cp.async double-buffered K/V, heavy-first ----------------
__global__ void k_attn(const float* __restrict__ Q, const float* __restrict__ Kg,
                       const float* __restrict__ Vg, float* __restrict__ out){
    const int BQ=32, BK=32;
    int qt = (int)gridDim.x - 1 - (int)blockIdx.x;   // heavy blocks first
    int h = blockIdx.y, kvh = h>>1;
    const float* Qh = Q + ((size_t)h*S_ + qt*BQ)*HD_;
    const float* Kh = Kg + (size_t)kvh*S_*HD_;
    const float* Vh = Vg + (size_t)kvh*S_*HD_;
    __shared__ __align__(16) float Qs[32][68];
    __shared__ __align__(16) float Ks[2][32][68];
    __shared__ __align__(16) float Vs[2][32][68];
    __shared__ float Ps[32][33];
    int tid = threadIdx.x;
    int r = tid>>3, cg = tid&7;
    for (int idx=tid; idx<BQ*16; idx+=256){
        int row = idx>>4, d4 = idx&15;
        *(float4*)&Qs[row][d4*4] = ((const float4*)(Qh + row*HD_))[d4];
    }
    uint32_t ksb = smem_u32(&Ks[0][0][0]);
    uint32_t vsb = smem_u32(&Vs[0][0][0]);
    const uint32_t BUFB = 32*68*4;
    int lrow0 = tid>>4, lc4 = tid&15;          // idx = tid: row tid>>4, chunk tid&15
    auto issueKV = [&](int kt){
        uint32_t bo = (uint32_t)(kt&1)*BUFB;
        #pragma unroll
        for (int hh=0; hh<2; hh++){
            int row = lrow0 + hh*16;
            uint32_t so = bo + (uint32_t)(row*68 + lc4*4)*4;
            const float* gk = Kh + (size_t)(kt*BK+row)*HD_ + lc4*4;
            const float* gv = Vh + (size_t)(kt*BK+row)*HD_ + lc4*4;
            cpa16(ksb + so, gk, 16);
            cpa16(vsb + so, gv, 16);
        }
        CP_COMMIT();
    };

    float o[8];
    #pragma unroll
    for (int i=0;i<8;i++) o[i]=0.f;
    float mrow=-1e30f, lrow=0.f;
    int ntiles = qt + 1;
    int qg = qt*BQ + r;

    issueKV(0);
    for (int kt=0; kt<ntiles; kt++){
        if (kt+1 < ntiles){ issueKV(kt+1); CP_WAIT1(); } else { CP_WAIT0(); }
        __syncthreads();
        const float (*Kb)[68] = Ks[kt&1];
        const float (*Vb)[68] = Vs[kt&1];
        float sc[4];
        #pragma unroll
        for (int j=0;j<4;j++) sc[j]=0.f;
        #pragma unroll
        for (int d4=0; d4<16; d4++){
            float4 qv = *(const float4*)&Qs[r][d4*4];
            #pragma unroll
            for (int j=0;j<4;j++){
                float4 kv = *(const float4*)&Kb[cg+8*j][d4*4];
                sc[j] += qv.x*kv.x + qv.y*kv.y + qv.z*kv.z + qv.w*kv.w;
            }
        }
        float tmax=-1e30f;
        #pragma unroll
        for (int j=0;j<4;j++){
            int kgl = kt*BK + cg + 8*j;
            sc[j] = (kgl<=qg) ? sc[j]*0.125f : -1e30f;
            tmax = fmaxf(tmax, sc[j]);
        }
        #pragma unroll
        for (int m=1;m<8;m<<=1) tmax = fmaxf(tmax, __shfl_xor_sync(0xffffffffu, tmax, m));
        float mnew = fmaxf(mrow, tmax);
        float fac = expf(mrow - mnew);
        float ps=0.f;
        #pragma unroll
        for (int j=0;j<4;j++){
            float p = expf(sc[j]-mnew);
            Ps[r][cg+8*j] = p;
            ps += p;
        }
        #pragma unroll
        for (int m=1;m<8;m<<=1) ps += __shfl_xor_sync(0xffffffffu, ps, m);
        lrow = lrow*fac + ps;
        mrow = mnew;
        #pragma unroll
        for (int i=0;i<8;i++) o[i]*=fac;
        __syncwarp();
        #pragma unroll 4
        for (int k=0;k<BK;k++){
            float p = Ps[r][k];
            const float4* vr = (const float4*)&Vb[k][cg*8];
            float4 v0 = vr[0], v1 = vr[1];
            o[0]+=p*v0.x; o[1]+=p*v0.y; o[2]+=p*v0.z; o[3]+=p*v0.w;
            o[4]+=p*v1.x; o[5]+=p*v1.y; o[6]+=p*v1.z; o[7]+=p*v1.w;
        }
        __syncthreads();
    }
    float inv = 1.f/lrow;
    float* orow = out + (size_t)(qt*BQ+r)*H_ + h*HD_ + cg*8;
    ((float4*)orow)[0] = make_float4(o[0]*inv,o[1]*inv,o[2]*inv,o[3]*inv);
    ((float4*)orow)[1] = make_float4(o[4]*inv,o[5]*inv,o[6]*inv,o[7]*inv);
}

__global__ void k_swiglu(const float* __restrict__ gu, float* __restrict__ act,
                         int rows_fixed, int use_total){
    int rows = use_total ? g_eoff[E_] : rows_fixed;
    long long total = (long long)rows * I_;
    for (long long idx = blockIdx.x*(long long)blockDim.x + threadIdx.x;
         idx < total; idx += (long long)gridDim.x*blockDim.x){
        int rr = (int)(idx / I_), cc = (int)(idx % I_);
        float a = gu[(size_t)rr*(2*I_) + cc];
        float b = gu[(size_t)rr*(2*I_) + I_ + cc];
        act[idx] = a * (b / (1.f + expf(-b)));
    }
}

__global__ void k_gate(const float* __restrict__ x2, const float* __restrict__ Wg){
    __shared__ float row[H_];
    int t = blockIdx.x, tid = threadIdx.x;
    for (int i=tid;i<H_/4;i+=64) ((float4*)row)[i] = ((const float4*)(x2+(size_t)t*H_))[i];
    __syncthreads();
    float acc=0.f;
    #pragma unroll 4
    for (int h=0;h<H_;h++) acc += row[h]*Wg[h*E_+tid];
    g_lg[t*E_+tid]=acc;
}

__global__ void k_topk(){
    int t = blockIdx.x, lane = threadIdx.x;
    float v0 = g_lg[t*E_+lane], v1 = g_lg[t*E_+32+lane];
    float topv[TK_]; int topi[TK_];
    #pragma unroll
    for (int k=0;k<TK_;k++){
        float bv; int bi;
        if (v0 >= v1){ bv=v0; bi=lane; } else { bv=v1; bi=lane+32; }
        #pragma unroll
        for (int m=16;m;m>>=1){
            float ov = __shfl_xor_sync(0xffffffffu, bv, m);
            int   oi = __shfl_xor_sync(0xffffffffu, bi, m);
            if (ov > bv || (ov==bv && oi<bi)){ bv=ov; bi=oi; }
        }
        topv[k]=bv; topi[k]=bi;
        if (bi==lane)    v0=-3.0e38f;
        if (bi==lane+32) v1=-3.0e38f;
    }
    if (lane==0){
        float m0 = topv[0], s=0.f, ex[TK_];
        #pragma unroll
        for (int k=0;k<TK_;k++){ ex[k]=expf(topv[k]-m0); s+=ex[k]; }
        float invs = 1.f/s;
        #pragma unroll
        for (int k=0;k<TK_;k++){ g_w8[t*TK_+k]=ex[k]*invs; g_idx8[t*TK_+k]=topi[k]; }
    }
}

__global__ void k_route(){
    int e = blockIdx.x, tid = threadIdx.x;
    __shared__ int sc[256];
    const int per = MAXPAIRS_/256;
    int base = tid*per, c=0;
    for (int j=0;j<per;j++) if (g_idx8[base+j]==e) c++;
    sc[tid]=c; __syncthreads();
    for (int off=1; off<256; off<<=1){
        int v = (tid>=off)? sc[tid-off] : 0;
        __syncthreads();
        sc[tid] += v;
        __syncthreads();
    }
    int p = sc[tid]-c;
    for (int j=0;j<per;j++){
        int i = base+j;
        if (g_idx8[i]==e){
            if (p < C_){ g_etok[e*C_+p] = i>>3; g_ppos[i]=p; }
            else g_ppos[i] = -1;
            p++;
        }
    }
    if (tid==255) g_ecnt[e] = min(sc[255], C_);
}

__global__ void k_offsets(){
    if (threadIdx.x==0){
        int s=0;
        for (int e=0;e<E_;e++){ g_eoff[e]=s; s+=g_ecnt[e]; }
        g_eoff[E_]=s;
    }
}

__global__ void k_combine(const float* __restrict__ h1, const float* __restrict__ sh,
                          float* __restrict__ out){
    int t = blockIdx.x, tid = threadIdx.x;
    size_t base = (size_t)t*H_ + tid*4;
    float4 a = *(const float4*)(h1+base);
    float4 b = *(const float4*)(sh+base);
    a.x+=b.x; a.y+=b.y; a.z+=b.z; a.w+=b.w;
    #pragma unroll
    for (int k=0;k<TK_;k++){
        int p = g_ppos[t*TK_+k];
        if (p>=0){
            int e = g_idx8[t*TK_+k];
            float w = g_w8[t*TK_+k];
            float4 y = ((const float4*)&g_ye[(size_t)(g_eoff[e]+p)*H_])[tid];
            a.x += w*y.x; a.y += w*y.y; a.z += w*y.z; a.w += w*y.w;
        }
    }
    *(float4*)(out+base) = a;
}

// ---------------- launch ----------------
extern "C" void kernel_launch(void* const* d_in, const int* in_sizes, int n_in,
                              void* d_out, int out_size){
    const float* hs    = (const float*)d_in[0];
    const float* cb    = (const float*)d_in[1];
    const float* sb    = (const float*)d_in[2];
    const float* ln1   = (const float*)d_in[3];
    const float* ln2   = (const float*)d_in[4];
    const float* Wqkv  = (const float*)d_in[5];
    const float* Wo    = (const float*)d_in[6];
    const float* qw    = (const float*)d_in[7];
    const float* kw    = (const float*)d_in[8];
    const float* Wgu_s = (const float*)d_in[9];
    const float* Wd_s  = (const float*)d_in[10];
    const float* Wgate = (const float*)d_in[11];
    const float* Wgu_e = (const float*)d_in[12];
    const float* Wd_e  = (const float*)d_in[13];
    float* out = (float*)d_out;

    float *p_xln,*p_qkv,*p_q,*p_k,*p_v,*p_attn,*p_h1,*p_x2,*p_gu,*p_act,*p_sh;
    cudaGetSymbolAddress((void**)&p_xln,  g_xln);
    cudaGetSymbolAddress((void**)&p_qkv,  g_qkv);
    cudaGetSymbolAddress((void**)&p_q,    g_q);
    cudaGetSymbolAddress((void**)&p_k,    g_k);
    cudaGetSymbolAddress((void**)&p_v,    g_v);
    cudaGetSymbolAddress((void**)&p_attn, g_attn);
    cudaGetSymbolAddress((void**)&p_h1,   g_h1);
    cudaGetSymbolAddress((void**)&p_x2,   g_x2);
    cudaGetSymbolAddress((void**)&p_gu,   g_gu);
    cudaGetSymbolAddress((void**)&p_act,  g_act);
    cudaGetSymbolAddress((void**)&p_sh,   g_sh);

    cudaFuncSetAttribute(k_tgemm,     cudaFuncAttributeMaxDynamicSharedMemorySize, SMEM_BYTES);
    cudaFuncSetAttribute(k_tgemm_egu, cudaFuncAttributeMaxDynamicSharedMemorySize, SMEM_BYTES);
    cudaFuncSetAttribute(k_tgemm_edn, cudaFuncAttributeMaxDynamicSharedMemorySize, SMEM_BYTES);

    k_rmsnorm<<<S_,256>>>(hs, ln1, p_xln);
    k_tgemm<<<dim3(2048/128, 8),128,SMEM_BYTES>>>(p_xln, H_, Wqkv, 2048, p_qkv, 2048, nullptr, S_, H_);
    k_rope<<<dim3(S_, NH_+KVH_),32>>>(p_qkv, cb, sb, qw, kw);
    k_attn<<<dim3(S_/32, NH_),256>>>(p_q, p_k, p_v, p_attn);
    k_tgemm<<<dim3(H_/128, 8),128,SMEM_BYTES>>>(p_attn, H_, Wo, H_, p_h1, H_, hs, S_, H_);
    k_rmsnorm<<<S_,256>>>(p_h1, ln2, p_x2);
    // shared MLP
    k_tgemm<<<dim3((2*I_)/128, 8),128,SMEM_BYTES>>>(p_x2, H_, Wgu_s, 2*I_, p_gu, 2*I_, nullptr, S_, H_);
    k_swiglu<<<2048,256>>>(p_gu, p_act, S_, 0);
    k_tgemm<<<dim3(H_/128, 8),128,SMEM_BYTES>>>(p_act, I_, Wd_s, H_, p_sh, H_, nullptr, S_, I_);
    // routing
    k_gate<<<S_,64>>>(p_x2, Wgate);
    k_topk<<<S_,32>>>();
    k_route<<<E_,256>>>();
    k_offsets<<<1,32>>>();
    // experts (compact, tf32 mma + cp.async)
    k_tgemm_egu<<<dim3((2*I_)/128, C_/128, E_),128,SMEM_BYTES>>>(p_x2, Wgu_e);
    k_swiglu<<<4096,256>>>(p_gu, p_act, 0, 1);
    k_tgemm_edn<<<dim3(H_/128, C_/128, E_),128,SMEM_BYTES>>>(Wd_e);
    k_combine<<<S_,256>>>(p_h1, p_sh, out);
}

// round 11
// speedup vs baseline: 1.1366x; 1.1366x over previous
#include <cuda_runtime.h>
#include <math.h>
#include <stdint.h>

#define S_   1024
#define H_   1024
#define NH_  16
#define KVH_ 8
#define HD_  64
#define E_   64
#define TK_  8
#define I_   3072
#define C_   512
#define MAXPAIRS_ (S_*TK_)

// ---------------- scratch ----------------
__device__ float g_xln [S_*H_];
__device__ float g_qkv [S_*2048];
__device__ float g_q   [NH_*S_*HD_];
__device__ float g_k   [KVH_*S_*HD_];
__device__ float g_v   [KVH_*S_*HD_];
__device__ float g_attn[S_*H_];
__device__ float g_h1  [S_*H_];
__device__ float g_x2  [S_*H_];
__device__ float g_gu  [(size_t)MAXPAIRS_*2*I_];
__device__ float g_act [(size_t)MAXPAIRS_*I_];
__device__ float g_sh  [S_*H_];
__device__ float g_lg  [S_*E_];
__device__ float g_w8  [S_*TK_];
__device__ int   g_idx8[S_*TK_];
__device__ int   g_ppos[S_*TK_];
__device__ int   g_etok[E_*C_];
__device__ int   g_ecnt[E_];
__device__ int   g_eoff[E_+1];
__device__ float g_ye  [(size_t)MAXPAIRS_*H_];

// ---------------- helpers ----------------
__device__ __forceinline__ uint32_t smem_u32(const void* p){
    uint32_t a;
    asm("{ .reg .u64 t; cvta.to.shared.u64 t, %1; cvt.u32.u64 %0, t; }" : "=r"(a) : "l"(p));
    return a;
}
__device__ __forceinline__ void mma_tf32(float* c, const uint32_t* a, const uint32_t* b){
    asm volatile("mma.sync.aligned.m16n8k8.row.col.f32.tf32.tf32.f32 "
        "{%0,%1,%2,%3}, {%4,%5,%6,%7}, {%8,%9}, {%0,%1,%2,%3};"
        : "+f"(c[0]), "+f"(c[1]), "+f"(c[2]), "+f"(c[3])
        : "r"(a[0]), "r"(a[1]), "r"(a[2]), "r"(a[3]), "r"(b[0]), "r"(b[1]));
}
__device__ __forceinline__ void ldsm_x4(uint32_t* r, uint32_t addr){
    asm volatile("ldmatrix.sync.aligned.m8n8.x4.shared.b16 {%0,%1,%2,%3}, [%4];"
        : "=r"(r[0]), "=r"(r[1]), "=r"(r[2]), "=r"(r[3]) : "r"(addr));
}
__device__ __forceinline__ void cpa16(uint32_t sm, const void* g, int sz){
    asm volatile("cp.async.cg.shared.global [%0], [%1], 16, %2;"
                 :: "r"(sm), "l"(g), "r"(sz) : "memory");
}
#define CP_COMMIT() asm volatile("cp.async.commit_group;" ::: "memory")
#define CP_WAIT2()  asm volatile("cp.async.wait_group 2;" ::: "memory")

// smem per stage (floats): As[128][20] + Bs[16][136]
#define AS_PITCH 20
#define BS_PITCH 136
#define ASZ (128*AS_PITCH)           // 2560
#define BSZ (16*BS_PITCH)            // 2176
#define STG_FLOATS (ASZ+BSZ)         // 4736
#define NSTG 4
#define SMEM_BYTES (NSTG*STG_FLOATS*4)  // 75776

extern __shared__ float dsmf[];

// ---------------- tf32 GEMM: 128x128 tile, 256 thr (8 warps, 64x32 each), 4-stage cp.async, LDSM A-frags ----------------
__device__ __forceinline__ void tgemm_core(
    const float* __restrict__ A, int lda, const int* __restrict__ gidx,
    const float* __restrict__ B, int ldb,
    float* __restrict__ Cc, int ldc, const float* __restrict__ res,
    int Mv, int Kd, int m0, int n0)
{
    int tid = threadIdx.x, lane = tid & 31, wid = tid >> 5;
    int wm = wid & 1, wn = wid >> 1;
    int gq = lane >> 2, lq = lane & 3;
    uint32_t smb = smem_u32(dsmf);

    // A-loader: row tid>>1, col half (tid&1)*8
    int arow = tid >> 1, acol = (tid & 1) * 8;
    int gr = m0 + arow;
    int rid = (gr < Mv) ? (gidx ? gidx[gr] : gr) : -1;
    const float* Arow = (rid >= 0) ? (A + (size_t)rid*lda + acol) : A;
    int asz = (rid >= 0) ? 16 : 0;
    // B-loader: rows bk, bk+8; cols lane*4
    int bk = tid >> 5, bn4 = lane * 4;
    const float* Bp = B + (size_t)bk*ldb + n0 + bn4;

    uint32_t aDst = smb + (uint32_t)(arow*AS_PITCH + acol)*4;
    uint32_t bDst = smb + (uint32_t)(ASZ + bk*BS_PITCH + bn4)*4;
    const uint32_t STRB = STG_FLOATS*4;

    // LDSM per-lane source mapping: row lane&15, col (lane>>4)*4
    int lrow = wm*64 + (lane & 15);
    int lcol = (lane >> 4) * 4;

    int T = Kd >> 4;

    float acc[4][4][4];
    #pragma unroll
    for (int i=0;i<4;i++)
        #pragma unroll
        for (int j=0;j<4;j++)
            #pragma unroll
            for (int q=0;q<4;q++) acc[i][j][q]=0.f;

    auto issue = [&](int t){
        uint32_t so = (uint32_t)(t & 3) * STRB;
        int k0 = t << 4;
        cpa16(aDst + so,      Arow + k0,     asz);
        cpa16(aDst + so + 16, Arow + k0 + 4, asz);
        cpa16(bDst + so,                 Bp + (size_t)k0*ldb,     16);
        cpa16(bDst + so + BS_PITCH*8*4,  Bp + (size_t)(k0+8)*ldb, 16);
        CP_COMMIT();
    };

    #pragma unroll
    for (int s=0; s<NSTG-1; s++){
        if (s < T) issue(s); else CP_COMMIT();
    }

    for (int t=0; t<T; t++){
        CP_WAIT2();
        __syncthreads();
        if (t + NSTG-1 < T) issue(t + NSTG-1); else CP_COMMIT();

        uint32_t stgb = smb + (uint32_t)(t&3)*STRB;
        const uint32_t* Bs = (const uint32_t*)(dsmf + (size_t)(t&3)*STG_FLOATS + ASZ);
        #pragma unroll
        for (int kk=0; kk<16; kk+=8){
            uint32_t a[4][4], b[4][2];
            #pragma unroll
            for (int i=0;i<4;i++){
                uint32_t ad = stgb + (uint32_t)((lrow + i*16)*AS_PITCH + kk + lcol)*4;
                ldsm_x4(a[i], ad);
            }
            #pragma unroll
            for (int j=0;j<4;j++){
                int col = wn*32 + j*8 + gq;
                int row = kk + lq;
                b[j][0] = Bs[row*BS_PITCH + col];
                b[j][1] = Bs[(row+4)*BS_PITCH + col];
            }
            #pragma unroll
            for (int i=0;i<4;i++)
                #pragma unroll
                for (int j=0;j<4;j++)
                    mma_tf32(acc[i][j], a[i], b[j]);
        }
    }

    #pragma unroll
    for (int i=0;i<4;i++){
        #pragma unroll
        for (int h=0;h<2;h++){
            int row = m0 + wm*64 + i*16 + gq + h*8;
            if (row < Mv){
                float* crow = Cc + (size_t)row*ldc;
                const float* rrow = res ? (res + (size_t)row*ldc) : nullptr;
                #pragma unroll
                for (int j=0;j<4;j++){
                    int cix = n0 + wn*32 + j*8 + lq*2;
                    float2 v = make_float2(acc[i][j][h*2], acc[i][j][h*2+1]);
                    if (rrow){
                        float2 rv = *(const float2*)(rrow + cix);
                        v.x += rv.x; v.y += rv.y;
                    }
                    *(float2*)(crow + cix) = v;
                }
            }
        }
    }
}

__global__ void __launch_bounds__(256,2)
k_tgemm(const float* A, int lda, const float* B, int ldb,
        float* Cc, int ldc, const float* res, int Mv, int Kd){
    tgemm_core(A, lda, nullptr, B, ldb, Cc, ldc, res, Mv, Kd,
               blockIdx.y*128, blockIdx.x*128);
}

__global__ void __launch_bounds__(256,2)
k_tgemm_egu(const float* X, const float* Wgu){
    int e = blockIdx.z, cnt = g_ecnt[e], m0 = blockIdx.y*128;
    if (m0 >= cnt) return;
    tgemm_core(X, H_, &g_etok[e*C_], Wgu + (size_t)e*H_*2*I_, 2*I_,
               &g_gu[(size_t)g_eoff[e]*2*I_], 2*I_, nullptr, cnt, H_,
               m0, blockIdx.x*128);
}

__global__ void __launch_bounds__(256,2)
k_tgemm_edn(const float* Wd){
    int e = blockIdx.z, cnt = g_ecnt[e], m0 = blockIdx.y*128;
    if (m0 >= cnt) return;
    int off = g_eoff[e];
    tgemm_core(&g_act[(size_t)off*I_], I_, nullptr, Wd + (size_t)e*I_*H_, H_,
               &g_ye[(size_t)off*H_], H_, nullptr, cnt, I_,
               m0, blockIdx.x*128);
}

// ---------------- elementwise / routing ----------------
__global__ void k_rmsnorm(const float* __restrict__ x, const float* __restrict__ w,
                          float* __restrict__ y){
    int row = blockIdx.x, tid = threadIdx.x;
    float4 xv = ((const float4*)(x + (size_t)row*H_))[tid];
    float ss = xv.x*xv.x + xv.y*xv.y + xv.z*xv.z + xv.w*xv.w;
    #pragma unroll
    for (int m=16;m;m>>=1) ss += __shfl_xor_sync(0xffffffffu, ss, m);
    __shared__ float wsum[8];
    if ((tid&31)==0) wsum[tid>>5]=ss;
    __syncthreads();
    if (tid<8){
        float v=wsum[tid];
        #pragma unroll
        for (int m=4;m;m>>=1) v+=__shfl_xor_sync(0xffu,v,m);
        if (tid==0) wsum[0]=v;
    }
    __syncthreads();
    float inv = rsqrtf(wsum[0]*(1.0f/H_) + 1e-6f);
    float4 wv = ((const float4*)w)[tid];
    ((float4*)(y + (size_t)row*H_))[tid] =
        make_float4(wv.x*xv.x*inv, wv.y*xv.y*inv, wv.z*xv.z*inv, wv.w*xv.w*inv);
}

__global__ void k_rope(const float* __restrict__ qkv, const float* __restrict__ cb,
                       const float* __restrict__ sb, const float* __restrict__ qw,
                       const float* __restrict__ kw){
    int s = blockIdx.x, y = blockIdx.y, lane = threadIdx.x;
    const float* base; float* outp; const float* w;
    if (y < NH_){
        int kvh = y>>1, g = y&1;
        base = qkv + (size_t)s*2048 + kvh*256 + g*64;
        outp = &g_q[((size_t)y*S_ + s)*HD_];
        w = qw;
    } else {
        int kvh = y - NH_;
        base = qkv + (size_t)s*2048 + kvh*256 + 128;
        outp = &g_k[((size_t)kvh*S_ + s)*HD_];
        w = kw;
        float* vo = &g_v[((size_t)kvh*S_ + s)*HD_];
        vo[lane] = base[64+lane]; vo[lane+32] = base[96+lane];
    }
    float x0 = base[lane], x1 = base[lane+32];
    float r0 = x0*cb[s*HD_+lane]    - x1*sb[s*HD_+lane];
    float r1 = x1*cb[s*HD_+32+lane] + x0*sb[s*HD_+32+lane];
    float ss = r0*r0 + r1*r1;
    #pragma unroll
    for (int m=16;m;m>>=1) ss += __shfl_xor_sync(0xffffffffu, ss, m);
    float inv = rsqrtf(ss*(1.f/HD_) + 1e-6f);
    outp[lane] = w[lane]*r0*inv;
    outp[lane+32] = w[lane+32]*r1*inv;
}

// ---------------- attention: BQ=32, BK=32 (R9 config) ----------------
__global__ void k_attn(const float* __restrict__ Q, const float* __restrict__ Kg,
                       const float* __restrict__ Vg, float* __restrict__ out){
    const int BQ=32, BK=32;
    int qt = blockIdx.x, h = blockIdx.y, kvh = h>>1;
    const float* Qh = Q + ((size_t)h*S_ + qt*BQ)*HD_;
    const float* Kh = Kg + (size_t)kvh*S_*HD_;
    const float* Vh = Vg + (size_t)kvh*S_*HD_;
    __shared__ __align__(16) float Qs[32][68];
    __shared__ __align__(16) float Ks[32][68];
    __shared__ __align__(16) float Vs[32][68];
    __shared__ float Ps[32][33];
    int tid = threadIdx.x;
    int r = tid>>3, cg = tid&7;
    for (int idx=tid; idx<BQ*16; idx+=256){
        int row = idx>>4, d4 = idx&15;
        *(float4*)&Qs[row][d4*4] = ((const float4*)(Qh + row*HD_))[d4];
    }
    float o[8];
    #pragma unroll
    for (int i=0;i<8;i++) o[i]=0.f;
    float mrow=-1e30f, lrow=0.f;
    int ntiles = qt + 1;
    int qg = qt*BQ + r;
    __syncthreads();
    for (int kt=0; kt<ntiles; kt++){
        __syncthreads();
        for (int idx=tid; idx<BK*16; idx+=256){
            int row = idx>>4, d4 = idx&15;
            *(float4*)&Ks[row][d4*4] = ((const float4*)(Kh + (kt*BK+row)*HD_))[d4];
            *(float4*)&Vs[row][d4*4] = ((const float4*)(Vh + (kt*BK+row)*HD_))[d4];
        }
        __syncthreads();
        float sc[4];
        #pragma unroll
        for (int j=0;j<4;j++) sc[j]=0.f;
        #pragma unroll
        for (int d4=0; d4<16; d4++){
            float4 qv = *(const float4*)&Qs[r][d4*4];
            #pragma unroll
            for (int j=0;j<4;j++){
                float4 kv = *(const float4*)&Ks[cg+8*j][d4*4];
                sc[j] += qv.x*kv.x + qv.y*kv.y + qv.z*kv.z + qv.w*kv.w;
            }
        }
        float tmax=-1e30f;
        #pragma unroll
        for (int j=0;j<4;j++){
            int kgl = kt*BK + cg + 8*j;
            sc[j] = (kgl<=qg) ? sc[j]*0.125f : -1e30f;
            tmax = fmaxf(tmax, sc[j]);
        }
        #pragma unroll
        for (int m=1;m<8;m<<=1) tmax = fmaxf(tmax, __shfl_xor_sync(0xffffffffu, tmax, m));
        float mnew = fmaxf(mrow, tmax);
        float fac = expf(mrow - mnew);
        float ps=0.f;
        #pragma unroll
        for (int j=0;j<4;j++){
            float p = expf(sc[j]-mnew);
            Ps[r][cg+8*j] = p;
            ps += p;
        }
        #pragma unroll
        for (int m=1;m<8;m<<=1) ps += __shfl_xor_sync(0xffffffffu, ps, m);
        lrow = lrow*fac + ps;
        mrow = mnew;
        #pragma unroll
        for (int i=0;i<8;i++) o[i]*=fac;
        __syncwarp();
        #pragma unroll 4
        for (int k=0;k<BK;k++){
            float p = Ps[r][k];
            const float4* vr = (const float4*)&Vs[k][cg*8];
            float4 v0 = vr[0], v1 = vr[1];
            o[0]+=p*v0.x; o[1]+=p*v0.y; o[2]+=p*v0.z; o[3]+=p*v0.w;
            o[4]+=p*v1.x; o[5]+=p*v1.y; o[6]+=p*v1.z; o[7]+=p*v1.w;
        }
    }
    float inv = 1.f/lrow;
    float* orow = out + (size_t)(qt*BQ+r)*H_ + h*HD_ + cg*8;
    ((float4*)orow)[0] = make_float4(o[0]*inv,o[1]*inv,o[2]*inv,o[3]*inv);
    ((float4*)orow)[1] = make_float4(o[4]*inv,o[5]*inv,o[6]*inv,o[7]*inv);
}

__global__ void k_swiglu(const float* __restrict__ gu, float* __restrict__ act,
                         int rows_fixed, int use_total){
    int rows = use_total ? g_eoff[E_] : rows_fixed;
    long long total = (long long)rows * I_;
    for (long long idx = blockIdx.x*(long long)blockDim.x + threadIdx.x;
         idx < total; idx += (long long)gridDim.x*blockDim.x){
        int rr = (int)(idx / I_), cc = (int)(idx % I_);
        float a = gu[(size_t)rr*(2*I_) + cc];
        float b = gu[(size_t)rr*(2*I_) + I_ + cc];
        act[idx] = a * (b / (1.f + expf(-b)));
    }
}

__global__ void k_gate(const float* __restrict__ x2, const float* __restrict__ Wg){
    __shared__ float row[H_];
    int t = blockIdx.x, tid = threadIdx.x;
    for (int i=tid;i<H_/4;i+=64) ((float4*)row)[i] = ((const float4*)(x2+(size_t)t*H_))[i];
    __syncthreads();
    float acc=0.f;
    #pragma unroll 4
    for (int h=0;h<H_;h++) acc += row[h]*Wg[h*E_+tid];
    g_lg[t*E_+tid]=acc;
}

__global__ void k_topk(){
    int t = blockIdx.x, lane = threadIdx.x;
    float v0 = g_lg[t*E_+lane], v1 = g_lg[t*E_+32+lane];
    float topv[TK_]; int topi[TK_];
    #pragma unroll
    for (int k=0;k<TK_;k++){
        float bv; int bi;
        if (v0 >= v1){ bv=v0; bi=lane; } else { bv=v1; bi=lane+32; }
        #pragma unroll
        for (int m=16;m;m>>=1){
            float ov = __shfl_xor_sync(0xffffffffu, bv, m);
            int   oi = __shfl_xor_sync(0xffffffffu, bi, m);
            if (ov > bv || (ov==bv && oi<bi)){ bv=ov; bi=oi; }
        }
        topv[k]=bv; topi[k]=bi;
        if (bi==lane)    v0=-3.0e38f;
        if (bi==lane+32) v1=-3.0e38f;
    }
    if (lane==0){
        float m0 = topv[0], s=0.f, ex[TK_];
        #pragma unroll
        for (int k=0;k<TK_;k++){ ex[k]=expf(topv[k]-m0); s+=ex[k]; }
        float invs = 1.f/s;
        #pragma unroll
        for (int k=0;k<TK_;k++){ g_w8[t*TK_+k]=ex[k]*invs; g_idx8[t*TK_+k]=topi[k]; }
    }
}

__global__ void k_route(){
    int e = blockIdx.x, tid = threadIdx.x;
    __shared__ int sc[256];
    const int per = MAXPAIRS_/256;
    int base = tid*per, c=0;
    for (int j=0;j<per;j++) if (g_idx8[base+j]==e) c++;
    sc[tid]=c; __syncthreads();
    for (int off=1; off<256; off<<=1){
        int v = (tid>=off)? sc[tid-off] : 0;
        __syncthreads();
        sc[tid] += v;
        __syncthreads();
    }
    int p = sc[tid]-c;
    for (int j=0;j<per;j++){
        int i = base+j;
        if (g_idx8[i]==e){
            if (p < C_){ g_etok[e*C_+p] = i>>3; g_ppos[i]=p; }
            else g_ppos[i] = -1;
            p++;
        }
    }
    if (tid==255) g_ecnt[e] = min(sc[255], C_);
}

__global__ void k_offsets(){
    if (threadIdx.x==0){
        int s=0;
        for (int e=0;e<E_;e++){ g_eoff[e]=s; s+=g_ecnt[e]; }
        g_eoff[E_]=s;
    }
}

__global__ void k_combine(const float* __restrict__ h1, const float* __restrict__ sh,
                          float* __restrict__ out){
    int t = blockIdx.x, tid = threadIdx.x;
    size_t base = (size_t)t*H_ + tid*4;
    float4 a = *(const float4*)(h1+base);
    float4 b = *(const float4*)(sh+base);
    a.x+=b.x; a.y+=b.y; a.z+=b.z; a.w+=b.w;
    #pragma unroll
    for (int k=0;k<TK_;k++){
        int p = g_ppos[t*TK_+k];
        if (p>=0){
            int e = g_idx8[t*TK_+k];
            float w = g_w8[t*TK_+k];
            float4 y = ((const float4*)&g_ye[(size_t)(g_eoff[e]+p)*H_])[tid];
            a.x += w*y.x; a.y += w*y.y; a.z += w*y.z; a.w += w*y.w;
        }
    }
    *(float4*)(out+base) = a;
}

// ---------------- launch ----------------
extern "C" void kernel_launch(void* const* d_in, const int* in_sizes, int n_in,
                              void* d_out, int out_size){
    const float* hs    = (const float*)d_in[0];
    const float* cb    = (const float*)d_in[1];
    const float* sb    = (const float*)d_in[2];
    const float* ln1   = (const float*)d_in[3];
    const float* ln2   = (const float*)d_in[4];
    const float* Wqkv  = (const float*)d_in[5];
    const float* Wo    = (const float*)d_in[6];
    const float* qw    = (const float*)d_in[7];
    const float* kw    = (const float*)d_in[8];
    const float* Wgu_s = (const float*)d_in[9];
    const float* Wd_s  = (const float*)d_in[10];
    const float* Wgate = (const float*)d_in[11];
    const float* Wgu_e = (const float*)d_in[12];
    const float* Wd_e  = (const float*)d_in[13];
    float* out = (float*)d_out;

    float *p_xln,*p_qkv,*p_q,*p_k,*p_v,*p_attn,*p_h1,*p_x2,*p_gu,*p_act,*p_sh;
    cudaGetSymbolAddress((void**)&p_xln,  g_xln);
    cudaGetSymbolAddress((void**)&p_qkv,  g_qkv);
    cudaGetSymbolAddress((void**)&p_q,    g_q);
    cudaGetSymbolAddress((void**)&p_k,    g_k);
    cudaGetSymbolAddress((void**)&p_v,    g_v);
    cudaGetSymbolAddress((void**)&p_attn, g_attn);
    cudaGetSymbolAddress((void**)&p_h1,   g_h1);
    cudaGetSymbolAddress((void**)&p_x2,   g_x2);
    cudaGetSymbolAddress((void**)&p_gu,   g_gu);
    cudaGetSymbolAddress((void**)&p_act,  g_act);
    cudaGetSymbolAddress((void**)&p_sh,   g_sh);

    cudaFuncSetAttribute(k_tgemm,     cudaFuncAttributeMaxDynamicSharedMemorySize, SMEM_BYTES);
    cudaFuncSetAttribute(k_tgemm_egu, cudaFuncAttributeMaxDynamicSharedMemorySize, SMEM_BYTES);
    cudaFuncSetAttribute(k_tgemm_edn, cudaFuncAttributeMaxDynamicSharedMemorySize, SMEM_BYTES);

    k_rmsnorm<<<S_,256>>>(hs, ln1, p_xln);
    k_tgemm<<<dim3(2048/128, 8),256,SMEM_BYTES>>>(p_xln, H_, Wqkv, 2048, p_qkv, 2048, nullptr, S_, H_);
    k_rope<<<dim3(S_, NH_+KVH_),32>>>(p_qkv, cb, sb, qw, kw);
    k_attn<<<dim3(S_/32, NH_),256>>>(p_q, p_k, p_v, p_attn);
    k_tgemm<<<dim3(H_/128, 8),256,SMEM_BYTES>>>(p_attn, H_, Wo, H_, p_h1, H_, hs, S_, H_);
    k_rmsnorm<<<S_,256>>>(p_h1, ln2, p_x2);
    // shared MLP
    k_tgemm<<<dim3((2*I_)/128, 8),256,SMEM_BYTES>>>(p_x2, H_, Wgu_s, 2*I_, p_gu, 2*I_, nullptr, S_, H_);
    k_swiglu<<<2048,256>>>(p_gu, p_act, S_, 0);
    k_tgemm<<<dim3(H_/128, 8),256,SMEM_BYTES>>>(p_act, I_, Wd_s, H_, p_sh, H_, nullptr, S_, I_);
    // routing
    k_gate<<<S_,64>>>(p_x2, Wgate);
    k_topk<<<S_,32>>>();
    k_route<<<E_,256>>>();
    k_offsets<<<1,32>>>();
    // experts (compact, tf32 mma + cp.async + LDSM)
    k_tgemm_egu<<<dim3((2*I_)/128, C_/128, E_),256,SMEM_BYTES>>>(p_x2, Wgu_e);
    k_swiglu<<<4096,256>>>(p_gu, p_act, 0, 1);
    k_tgemm_edn<<<dim3(H_/128, C_/128, E_),256,SMEM_BYTES>>>(Wd_e);
    k_combine<<<S_,256>>>(p_h1, p_sh, out);
}

// round 13
// speedup vs baseline: 1.2552x; 1.1043x over previous
#include <cuda_runtime.h>
#include <math.h>
#include <stdint.h>

#define S_   1024
#define H_   1024
#define NH_  16
#define KVH_ 8
#define HD_  64
#define E_   64
#define TK_  8
#define I_   3072
#define C_   512
#define MAXPAIRS_ (S_*TK_)

// ---------------- scratch ----------------
__device__ float g_xln [S_*H_];
__device__ float g_qkv [S_*2048];
__device__ float g_q   [NH_*S_*HD_];
__device__ float g_k   [KVH_*S_*HD_];
__device__ float g_v   [KVH_*S_*HD_];
__device__ float g_attn[S_*H_];
__device__ float g_h1  [S_*H_];
__device__ float g_x2  [S_*H_];
__device__ float g_gu  [(size_t)MAXPAIRS_*2*I_];
__device__ float g_act [(size_t)MAXPAIRS_*I_];
__device__ float g_gu_s [(size_t)S_*2*I_];
__device__ float g_act_s[(size_t)S_*I_];
__device__ float g_sh  [S_*H_];
__device__ float g_lg  [S_*E_];
__device__ float g_w8  [S_*TK_];
__device__ int   g_idx8[S_*TK_];
__device__ int   g_ppos[S_*TK_];
__device__ int   g_etok[E_*C_];
__device__ int   g_ecnt[E_];
__device__ int   g_eoff[E_+1];
__device__ float g_ye  [(size_t)MAXPAIRS_*H_];

// ---------------- helpers ----------------
__device__ __forceinline__ uint32_t smem_u32(const void* p){
    uint32_t a;
    asm("{ .reg .u64 t; cvta.to.shared.u64 t, %1; cvt.u32.u64 %0, t; }" : "=r"(a) : "l"(p));
    return a;
}
__device__ __forceinline__ void mma_tf32(float* c, const uint32_t* a, const uint32_t* b){
    asm volatile("mma.sync.aligned.m16n8k8.row.col.f32.tf32.tf32.f32 "
        "{%0,%1,%2,%3}, {%4,%5,%6,%7}, {%8,%9}, {%0,%1,%2,%3};"
        : "+f"(c[0]), "+f"(c[1]), "+f"(c[2]), "+f"(c[3])
        : "r"(a[0]), "r"(a[1]), "r"(a[2]), "r"(a[3]), "r"(b[0]), "r"(b[1]));
}
__device__ __forceinline__ void cpa16(uint32_t sm, const void* g, int sz){
    asm volatile("cp.async.cg.shared.global [%0], [%1], 16, %2;"
                 :: "r"(sm), "l"(g), "r"(sz) : "memory");
}
#define CP_COMMIT() asm volatile("cp.async.commit_group;" ::: "memory")
#define CP_WAIT2()  asm volatile("cp.async.wait_group 2;" ::: "memory")

// smem per stage (floats): As[128][20] + Bs[16][136]
#define AS_PITCH 20
#define BS_PITCH 136
#define ASZ (128*AS_PITCH)
#define BSZ (16*BS_PITCH)
#define STG_FLOATS (ASZ+BSZ)
#define NSTG 4
#define SMEM_BYTES (NSTG*STG_FLOATS*4)  // 75776

extern __shared__ float dsmf[];

// ---------------- tf32 GEMM: 128x128 tile, 256 thr (8 warps, 64x32), 4-stage cp.async (R9 core) ----------------
__device__ __forceinline__ void tgemm_core(
    const float* __restrict__ A, int lda, const int* __restrict__ gidx,
    const float* __restrict__ B, int ldb,
    float* __restrict__ Cc, int ldc, const float* __restrict__ res,
    int Mv, int Kd, int m0, int n0)
{
    int tid = threadIdx.x, lane = tid & 31, wid = tid >> 5;
    int wm = wid & 1, wn = wid >> 1;
    int gq = lane >> 2, lq = lane & 3;
    uint32_t smb = smem_u32(dsmf);

    int arow = tid >> 1, acol = (tid & 1) * 8;
    int gr = m0 + arow;
    int rid = (gr < Mv) ? (gidx ? gidx[gr] : gr) : -1;
    const float* Arow = (rid >= 0) ? (A + (size_t)rid*lda + acol) : A;
    int asz = (rid >= 0) ? 16 : 0;
    int bk = tid >> 5, bn4 = lane * 4;
    const float* Bp = B + (size_t)bk*ldb + n0 + bn4;

    uint32_t aDst = smb + (uint32_t)(arow*AS_PITCH + acol)*4;
    uint32_t bDst = smb + (uint32_t)(ASZ + bk*BS_PITCH + bn4)*4;
    const uint32_t STRB = STG_FLOATS*4;

    int T = Kd >> 4;

    float acc[4][4][4];
    #pragma unroll
    for (int i=0;i<4;i++)
        #pragma unroll
        for (int j=0;j<4;j++)
            #pragma unroll
            for (int q=0;q<4;q++) acc[i][j][q]=0.f;

    auto issue = [&](int t){
        uint32_t so = (uint32_t)(t & 3) * STRB;
        int k0 = t << 4;
        cpa16(aDst + so,      Arow + k0,     asz);
        cpa16(aDst + so + 16, Arow + k0 + 4, asz);
        cpa16(bDst + so,                 Bp + (size_t)k0*ldb,     16);
        cpa16(bDst + so + BS_PITCH*8*4,  Bp + (size_t)(k0+8)*ldb, 16);
        CP_COMMIT();
    };

    #pragma unroll
    for (int s=0; s<NSTG-1; s++){
        if (s < T) issue(s); else CP_COMMIT();
    }

    for (int t=0; t<T; t++){
        CP_WAIT2();
        __syncthreads();
        if (t + NSTG-1 < T) issue(t + NSTG-1); else CP_COMMIT();

        const uint32_t* As = (const uint32_t*)(dsmf + (size_t)(t&3)*STG_FLOATS);
        const uint32_t* Bs = As + ASZ;
        #pragma unroll
        for (int kk=0; kk<16; kk+=8){
            uint32_t a[4][4], b[4][2];
            #pragma unroll
            for (int i=0;i<4;i++){
                int rb = wm*64 + i*16 + gq;
                int c  = kk + lq;
                a[i][0] = As[rb*AS_PITCH + c];
                a[i][1] = As[(rb+8)*AS_PITCH + c];
                a[i][2] = As[rb*AS_PITCH + c + 4];
                a[i][3] = As[(rb+8)*AS_PITCH + c + 4];
            }
            #pragma unroll
            for (int j=0;j<4;j++){
                int col = wn*32 + j*8 + gq;
                int row = kk + lq;
                b[j][0] = Bs[row*BS_PITCH + col];
                b[j][1] = Bs[(row+4)*BS_PITCH + col];
            }
            #pragma unroll
            for (int i=0;i<4;i++)
                #pragma unroll
                for (int j=0;j<4;j++)
                    mma_tf32(acc[i][j], a[i], b[j]);
        }
    }

    #pragma unroll
    for (int i=0;i<4;i++){
        #pragma unroll
        for (int h=0;h<2;h++){
            int row = m0 + wm*64 + i*16 + gq + h*8;
            if (row < Mv){
                float* crow = Cc + (size_t)row*ldc;
                const float* rrow = res ? (res + (size_t)row*ldc) : nullptr;
                #pragma unroll
                for (int j=0;j<4;j++){
                    int cix = n0 + wn*32 + j*8 + lq*2;
                    float2 v = make_float2(acc[i][j][h*2], acc[i][j][h*2+1]);
                    if (rrow){
                        float2 rv = *(const float2*)(rrow + cix);
                        v.x += rv.x; v.y += rv.y;
                    }
                    *(float2*)(crow + cix) = v;
                }
            }
        }
    }
}

__global__ void __launch_bounds__(256,2)
k_tgemm(const float* A, int lda, const float* B, int ldb,
        float* Cc, int ldc, const float* res, int Mv, int Kd){
    tgemm_core(A, lda, nullptr, B, ldb, Cc, ldc, res, Mv, Kd,
               blockIdx.y*128, blockIdx.x*128);
}

// fused: z<E_ -> expert e ; z==E_ -> shared MLP (gu)
__global__ void __launch_bounds__(256,2)
k_tgemm_egu(const float* X, const float* Wgu, const float* Wgu_s){
    int z = blockIdx.z, m0 = blockIdx.y*128;
    if (z < E_){
        int cnt = g_ecnt[z];
        if (m0 >= cnt) return;
        tgemm_core(X, H_, &g_etok[z*C_], Wgu + (size_t)z*H_*2*I_, 2*I_,
                   &g_gu[(size_t)g_eoff[z]*2*I_], 2*I_, nullptr, cnt, H_,
                   m0, blockIdx.x*128);
    } else {
        tgemm_core(X, H_, nullptr, Wgu_s, 2*I_,
                   g_gu_s, 2*I_, nullptr, S_, H_,
                   m0, blockIdx.x*128);
    }
}

__global__ void __launch_bounds__(256,2)
k_tgemm_edn(const float* Wd, const float* Wd_s){
    int z = blockIdx.z, m0 = blockIdx.y*128;
    if (z < E_){
        int cnt = g_ecnt[z];
        if (m0 >= cnt) return;
        int off = g_eoff[z];
        tgemm_core(&g_act[(size_t)off*I_], I_, nullptr, Wd + (size_t)z*I_*H_, H_,
                   &g_ye[(size_t)off*H_], H_, nullptr, cnt, I_,
                   m0, blockIdx.x*128);
    } else {
        tgemm_core(g_act_s, I_, nullptr, Wd_s, H_,
                   g_sh, H_, nullptr, S_, I_,
                   m0, blockIdx.x*128);
    }
}

// ---------------- elementwise / routing ----------------
__global__ void k_rmsnorm(const float* __restrict__ x, const float* __restrict__ w,
                          float* __restrict__ y){
    int row = blockIdx.x, tid = threadIdx.x;
    float4 xv = ((const float4*)(x + (size_t)row*H_))[tid];
    float ss = xv.x*xv.x + xv.y*xv.y + xv.z*xv.z + xv.w*xv.w;
    #pragma unroll
    for (int m=16;m;m>>=1) ss += __shfl_xor_sync(0xffffffffu, ss, m);
    __shared__ float wsum[8];
    if ((tid&31)==0) wsum[tid>>5]=ss;
    __syncthreads();
    if (tid<8){
        float v=wsum[tid];
        #pragma unroll
        for (int m=4;m;m>>=1) v+=__shfl_xor_sync(0xffu,v,m);
        if (tid==0) wsum[0]=v;
    }
    __syncthreads();
    float inv = rsqrtf(wsum[0]*(1.0f/H_) + 1e-6f);
    float4 wv = ((const float4*)w)[tid];
    ((float4*)(y + (size_t)row*H_))[tid] =
        make_float4(wv.x*xv.x*inv, wv.y*xv.y*inv, wv.z*xv.z*inv, wv.w*xv.w*inv);
}

__global__ void k_rope(const float* __restrict__ qkv, const float* __restrict__ cb,
                       const float* __restrict__ sb, const float* __restrict__ qw,
                       const float* __restrict__ kw){
    int s = blockIdx.x, y = blockIdx.y, lane = threadIdx.x;
    const float* base; float* outp; const float* w;
    if (y < NH_){
        int kvh = y>>1, g = y&1;
        base = qkv + (size_t)s*2048 + kvh*256 + g*64;
        outp = &g_q[((size_t)y*S_ + s)*HD_];
        w = qw;
    } else {
        int kvh = y - NH_;
        base = qkv + (size_t)s*2048 + kvh*256 + 128;
        outp = &g_k[((size_t)kvh*S_ + s)*HD_];
        w = kw;
        float* vo = &g_v[((size_t)kvh*S_ + s)*HD_];
        vo[lane] = base[64+lane]; vo[lane+32] = base[96+lane];
    }
    float x0 = base[lane], x1 = base[lane+32];
    float r0 = x0*cb[s*HD_+lane]    - x1*sb[s*HD_+lane];
    float r1 = x1*cb[s*HD_+32+lane] + x0*sb[s*HD_+32+lane];
    float ss = r0*r0 + r1*r1;
    #pragma unroll
    for (int m=16;m;m>>=1) ss += __shfl_xor_sync(0xffffffffu, ss, m);
    float inv = rsqrtf(ss*(1.f/HD_) + 1e-6f);
    outp[lane] = w[lane]*r0*inv;
    outp[lane+32] = w[lane+32]*r1*inv;
}

// ---------------- attention: BQ=16, BK=32, 1024 blocks, heavy-first ----------------
__global__ void k_attn(const float* __restrict__ Q, const float* __restrict__ Kg,
                       const float* __restrict__ Vg, float* __restrict__ out){
    const int BQ=16, BK=32;
    int qt = (int)gridDim.x - 1 - (int)blockIdx.x;
    int h = blockIdx.y, kvh = h>>1;
    const float* Qh = Q + ((size_t)h*S_ + qt*BQ)*HD_;
    const float* Kh = Kg + (size_t)kvh*S_*HD_;
    const float* Vh = Vg + (size_t)kvh*S_*HD_;
    __shared__ __align__(16) float Qs[16][68];
    __shared__ __align__(16) float Ks[32][68];
    __shared__ __align__(16) float Vs[32][68];
    __shared__ float Ps[16][33];
    int tid = threadIdx.x;
    int r = tid>>4, cg = tid&15;          // 16 threads per query row
    {   // load Q: exactly 256 chunks
        int row = tid>>4, d4 = tid&15;
        *(float4*)&Qs[row][d4*4] = ((const float4*)(Qh + row*HD_))[d4];
    }
    float o[4] = {0.f,0.f,0.f,0.f};
    float mrow=-1e30f, lrow=0.f;
    int ntiles = (qt+2)>>1;
    int qg = qt*BQ + r;
    __syncthreads();
    for (int kt=0; kt<ntiles; kt++){
        __syncthreads();
        for (int idx=tid; idx<BK*16; idx+=256){
            int row = idx>>4, d4 = idx&15;
            *(float4*)&Ks[row][d4*4] = ((const float4*)(Kh + (kt*BK+row)*HD_))[d4];
            *(float4*)&Vs[row][d4*4] = ((const float4*)(Vh + (kt*BK+row)*HD_))[d4];
        }
        __syncthreads();
        float sc[2]; sc[0]=0.f; sc[1]=0.f;
        #pragma unroll
        for (int d4=0; d4<16; d4++){
            float4 qv = *(const float4*)&Qs[r][d4*4];
            #pragma unroll
            for (int j=0;j<2;j++){
                float4 kv = *(const float4*)&Ks[cg+16*j][d4*4];
                sc[j] += qv.x*kv.x + qv.y*kv.y + qv.z*kv.z + qv.w*kv.w;
            }
        }
        float tmax=-1e30f;
        #pragma unroll
        for (int j=0;j<2;j++){
            int kgl = kt*BK + cg + 16*j;
            sc[j] = (kgl<=qg) ? sc[j]*0.125f : -1e30f;
            tmax = fmaxf(tmax, sc[j]);
        }
        #pragma unroll
        for (int m=1;m<16;m<<=1) tmax = fmaxf(tmax, __shfl_xor_sync(0xffffffffu, tmax, m));
        float mnew = fmaxf(mrow, tmax);
        float fac = expf(mrow - mnew);
        float ps=0.f;
        #pragma unroll
        for (int j=0;j<2;j++){
            float p = expf(sc[j]-mnew);
            Ps[r][cg+16*j] = p;
            ps += p;
        }
        #pragma unroll
        for (int m=1;m<16;m<<=1) ps += __shfl_xor_sync(0xffffffffu, ps, m);
        lrow = lrow*fac + ps;
        mrow = mnew;
        o[0]*=fac; o[1]*=fac; o[2]*=fac; o[3]*=fac;
        __syncwarp();
        #pragma unroll 8
        for (int k=0;k<BK;k++){
            float p = Ps[r][k];
            float4 v = *(const float4*)&Vs[k][cg*4];
            o[0]+=p*v.x; o[1]+=p*v.y; o[2]+=p*v.z; o[3]+=p*v.w;
        }
    }
    float inv = 1.f/lrow;
    float* orow = out + (size_t)(qt*BQ+r)*H_ + h*HD_ + cg*4;
    *(float4*)orow = make_float4(o[0]*inv,o[1]*inv,o[2]*inv,o[3]*inv);
}

// fused swiglu over expert rows then shared rows
__global__ void k_swiglu(){
    int rows_e = g_eoff[E_];
    long long total = (long long)(rows_e + S_) * I_;
    for (long long idx = blockIdx.x*(long long)blockDim.x + threadIdx.x;
         idx < total; idx += (long long)gridDim.x*blockDim.x){
        int rr = (int)(idx / I_), cc = (int)(idx % I_);
        if (rr < rows_e){
            float a = g_gu[(size_t)rr*(2*I_) + cc];
            float b = g_gu[(size_t)rr*(2*I_) + I_ + cc];
            g_act[(size_t)rr*I_ + cc] = a * (b / (1.f + expf(-b)));
        } else {
            int rs = rr - rows_e;
            float a = g_gu_s[(size_t)rs*(2*I_) + cc];
            float b = g_gu_s[(size_t)rs*(2*I_) + I_ + cc];
            g_act_s[(size_t)rs*I_ + cc] = a * (b / (1.f + expf(-b)));
        }
    }
}

__global__ void k_gate(const float* __restrict__ x2, const float* __restrict__ Wg){
    __shared__ float row[H_];
    int t = blockIdx.x, tid = threadIdx.x;
    for (int i=tid;i<H_/4;i+=64) ((float4*)row)[i] = ((const float4*)(x2+(size_t)t*H_))[i];
    __syncthreads();
    float acc=0.f;
    #pragma unroll 4
    for (int h=0;h<H_;h++) acc += row[h]*Wg[h*E_+tid];
    g_lg[t*E_+tid]=acc;
}

__global__ void k_topk(){
    int t = blockIdx.x, lane = threadIdx.x;
    float v0 = g_lg[t*E_+lane], v1 = g_lg[t*E_+32+lane];
    float topv[TK_]; int topi[TK_];
    #pragma unroll
    for (int k=0;k<TK_;k++){
        float bv; int bi;
        if (v0 >= v1){ bv=v0; bi=lane; } else { bv=v1; bi=lane+32; }
        #pragma unroll
        for (int m=16;m;m>>=1){
            float ov = __shfl_xor_sync(0xffffffffu, bv, m);
            int   oi = __shfl_xor_sync(0xffffffffu, bi, m);
            if (ov > bv || (ov==bv && oi<bi)){ bv=ov; bi=oi; }
        }
        topv[k]=bv; topi[k]=bi;
        if (bi==lane)    v0=-3.0e38f;
        if (bi==lane+32) v1=-3.0e38f;
    }
    if (lane==0){
        float m0 = topv[0], s=0.f, ex[TK_];
        #pragma unroll
        for (int k=0;k<TK_;k++){ ex[k]=expf(topv[k]-m0); s+=ex[k]; }
        float invs = 1.f/s;
        #pragma unroll
        for (int k=0;k<TK_;k++){ g_w8[t*TK_+k]=ex[k]*invs; g_idx8[t*TK_+k]=topi[k]; }
    }
}

__global__ void k_route(){
    int e = blockIdx.x, tid = threadIdx.x;
    __shared__ int sc[256];
    const int per = MAXPAIRS_/256;
    int base = tid*per, c=0;
    for (int j=0;j<per;j++) if (g_idx8[base+j]==e) c++;
    sc[tid]=c; __syncthreads();
    for (int off=1; off<256; off<<=1){
        int v = (tid>=off)? sc[tid-off] : 0;
        __syncthreads();
        sc[tid] += v;
        __syncthreads();
    }
    int p = sc[tid]-c;
    for (int j=0;j<per;j++){
        int i = base+j;
        if (g_idx8[i]==e){
            if (p < C_){ g_etok[e*C_+p] = i>>3; g_ppos[i]=p; }
            else g_ppos[i] = -1;
            p++;
        }
    }
    if (tid==255) g_ecnt[e] = min(sc[255], C_);
}

__global__ void k_offsets(){
    if (threadIdx.x==0){
        int s=0;
        for (int e=0;e<E_;e++){ g_eoff[e]=s; s+=g_ecnt[e]; }
        g_eoff[E_]=s;
    }
}

__global__ void k_combine(const float* __restrict__ h1, const float* __restrict__ sh,
                          float* __restrict__ out){
    int t = blockIdx.x, tid = threadIdx.x;
    size_t base = (size_t)t*H_ + tid*4;
    float4 a = *(const float4*)(h1+base);
    float4 b = *(const float4*)(sh+base);
    a.x+=b.x; a.y+=b.y; a.z+=b.z; a.w+=b.w;
    #pragma unroll
    for (int k=0;k<TK_;k++){
        int p = g_ppos[t*TK_+k];
        if (p>=0){
            int e = g_idx8[t*TK_+k];
            float w = g_w8[t*TK_+k];
            float4 y = ((const float4*)&g_ye[(size_t)(g_eoff[e]+p)*H_])[tid];
            a.x += w*y.x; a.y += w*y.y; a.z += w*y.z; a.w += w*y.w;
        }
    }
    *(float4*)(out+base) = a;
}

// ---------------- launch ----------------
extern "C" void kernel_launch(void* const* d_in, const int* in_sizes, int n_in,
                              void* d_out, int out_size){
    const float* hs    = (const float*)d_in[0];
    const float* cb    = (const float*)d_in[1];
    const float* sb    = (const float*)d_in[2];
    const float* ln1   = (const float*)d_in[3];
    const float* ln2   = (const float*)d_in[4];
    const float* Wqkv  = (const float*)d_in[5];
    const float* Wo    = (const float*)d_in[6];
    const float* qw    = (const float*)d_in[7];
    const float* kw    = (const float*)d_in[8];
    const float* Wgu_s = (const float*)d_in[9];
    const float* Wd_s  = (const float*)d_in[10];
    const float* Wgate = (const float*)d_in[11];
    const float* Wgu_e = (const float*)d_in[12];
    const float* Wd_e  = (const float*)d_in[13];
    float* out = (float*)d_out;

    float *p_xln,*p_qkv,*p_q,*p_k,*p_v,*p_attn,*p_h1,*p_x2;
    cudaGetSymbolAddress((void**)&p_xln,  g_xln);
    cudaGetSymbolAddress((void**)&p_qkv,  g_qkv);
    cudaGetSymbolAddress((void**)&p_q,    g_q);
    cudaGetSymbolAddress((void**)&p_k,    g_k);
    cudaGetSymbolAddress((void**)&p_v,    g_v);
    cudaGetSymbolAddress((void**)&p_attn, g_attn);
    cudaGetSymbolAddress((void**)&p_h1,   g_h1);
    cudaGetSymbolAddress((void**)&p_x2,   g_x2);
    float *p_sh;
    cudaGetSymbolAddress((void**)&p_sh,   g_sh);

    cudaFuncSetAttribute(k_tgemm,     cudaFuncAttributeMaxDynamicSharedMemorySize, SMEM_BYTES);
    cudaFuncSetAttribute(k_tgemm_egu, cudaFuncAttributeMaxDynamicSharedMemorySize, SMEM_BYTES);
    cudaFuncSetAttribute(k_tgemm_edn, cudaFuncAttributeMaxDynamicSharedMemorySize, SMEM_BYTES);

    k_rmsnorm<<<S_,256>>>(hs, ln1, p_xln);
    k_tgemm<<<dim3(2048/128, 8),256,SMEM_BYTES>>>(p_xln, H_, Wqkv, 2048, p_qkv, 2048, nullptr, S_, H_);
    k_rope<<<dim3(S_, NH_+KVH_),32>>>(p_qkv, cb, sb, qw, kw);
    k_attn<<<dim3(S_/16, NH_),256>>>(p_q, p_k, p_v, p_attn);
    k_tgemm<<<dim3(H_/128, 8),256,SMEM_BYTES>>>(p_attn, H_, Wo, H_, p_h1, H_, hs, S_, H_);
    k_rmsnorm<<<S_,256>>>(p_h1, ln2, p_x2);
    // routing (tiny, before fused GEMMs)
    k_gate<<<S_,64>>>(p_x2, Wgate);
    k_topk<<<S_,32>>>();
    k_route<<<E_,256>>>();
    k_offsets<<<1,32>>>();
    // fused expert + shared-MLP GEMMs
    k_tgemm_egu<<<dim3((2*I_)/128, 8, E_+1),256,SMEM_BYTES>>>(p_x2, Wgu_e, Wgu_s);
    k_swiglu<<<6144,256>>>();
    k_tgemm_edn<<<dim3(H_/128, 8, E_+1),256,SMEM_BYTES>>>(Wd_e, Wd_s);
    k_combine<<<S_,256>>>(p_h1, p_sh, out);
}

// round 14
// speedup vs baseline: 1.6938x; 1.3494x over previous
#include <cuda_runtime.h>
#include <cuda_fp16.h>
#include <math.h>
#include <stdint.h>

#define S_   1024
#define H_   1024
#define NH_  16
#define KVH_ 8
#define HD_  64
#define E_   64
#define TK_  8
#define I_   3072
#define C_   512
#define MAXPAIRS_ (S_*TK_)

// ---------------- scratch ----------------
__device__ __half g_xln16 [S_*H_];
__device__ float  g_qkv   [S_*2048];
__device__ float  g_q     [NH_*S_*HD_];
__device__ float  g_k     [KVH_*S_*HD_];
__device__ float  g_v     [KVH_*S_*HD_];
__device__ __half g_attn16[S_*H_];
__device__ float  g_h1    [S_*H_];
__device__ float  g_x2    [S_*H_];
__device__ __half g_x216  [S_*H_];
__device__ float  g_gu    [(size_t)MAXPAIRS_*2*I_];
__device__ __half g_act16 [(size_t)MAXPAIRS_*I_];
__device__ float  g_gu_s  [(size_t)S_*2*I_];
__device__ __half g_act_s16[(size_t)S_*I_];
__device__ float  g_sh    [S_*H_];
__device__ float  g_lg    [S_*E_];
__device__ float  g_w8    [S_*TK_];
__device__ int    g_idx8  [S_*TK_];
__device__ int    g_ppos  [S_*TK_];
__device__ int    g_etok  [E_*C_];
__device__ int    g_ecnt  [E_];
__device__ int    g_eoff  [E_+1];
__device__ float  g_ye    [(size_t)MAXPAIRS_*H_];

// ---------------- helpers ----------------
__device__ __forceinline__ uint32_t smem_u32(const void* p){
    uint32_t a;
    asm("{ .reg .u64 t; cvta.to.shared.u64 t, %1; cvt.u32.u64 %0, t; }" : "=r"(a) : "l"(p));
    return a;
}
__device__ __forceinline__ void mma_f16(float* c, const uint32_t* a, const uint32_t* b){
    asm volatile("mma.sync.aligned.m16n8k16.row.col.f32.f16.f16.f32 "
        "{%0,%1,%2,%3}, {%4,%5,%6,%7}, {%8,%9}, {%0,%1,%2,%3};"
        : "+f"(c[0]), "+f"(c[1]), "+f"(c[2]), "+f"(c[3])
        : "r"(a[0]), "r"(a[1]), "r"(a[2]), "r"(a[3]), "r"(b[0]), "r"(b[1]));
}
__device__ __forceinline__ void ldsm_x4(uint32_t* r, uint32_t addr){
    asm volatile("ldmatrix.sync.aligned.m8n8.x4.shared.b16 {%0,%1,%2,%3}, [%4];"
        : "=r"(r[0]), "=r"(r[1]), "=r"(r[2]), "=r"(r[3]) : "r"(addr));
}
__device__ __forceinline__ void cpa16(uint32_t sm, const void* g, int sz){
    asm volatile("cp.async.cg.shared.global [%0], [%1], 16, %2;"
                 :: "r"(sm), "l"(g), "r"(sz) : "memory");
}
#define CP_COMMIT() asm volatile("cp.async.commit_group;" ::: "memory")
#define CP_WAIT2()  asm volatile("cp.async.wait_group 2;" ::: "memory")

// smem per stage: A fp16 [128][24] + B fp32 [16][132]
#define AP16 24
#define A_BYTES (128*AP16*2)        // 6144
#define BS_PITCH 132
#define B_BYTES (16*BS_PITCH*4)     // 8448
#define STG_BYTES (A_BYTES+B_BYTES) // 14592
#define NSTG 4
#define SMEM_BYTES (NSTG*STG_BYTES) // 58368

extern __shared__ float dsmf[];

// ---------------- fp16 tensor GEMM: 128x128 tile, 256 thr, 4-stage cp.async ----------------
__device__ __forceinline__ void tgemm_core(
    const __half* __restrict__ A, int lda, const int* __restrict__ gidx,
    const float* __restrict__ B, int ldb,
    float* __restrict__ Cc, int ldc, const float* __restrict__ res,
    int Mv, int Kd, int m0, int n0)
{
    int tid = threadIdx.x, lane = tid & 31, wid = tid >> 5;
    int wm = wid & 1, wn = wid >> 1;
    int gq = lane >> 2, lq = lane & 3;
    uint32_t smb = smem_u32(dsmf);

    // A-loader: row tid>>1, half-offset (tid&1)*8 (one 16B cp = 8 halves)
    int arow = tid >> 1, acol = (tid & 1) * 8;
    int gr = m0 + arow;
    int rid = (gr < Mv) ? (gidx ? gidx[gr] : gr) : -1;
    const __half* Arow = (rid >= 0) ? (A + (size_t)rid*lda + acol) : A;
    int asz = (rid >= 0) ? 16 : 0;
    // B-loader: rows bk, bk+8 (fp32); cols lane*4
    int bk = tid >> 5, bn4 = lane * 4;
    const float* Bp = B + (size_t)bk*ldb + n0 + bn4;

    uint32_t aDst = smb + (uint32_t)(arow*AP16 + acol)*2;
    uint32_t bDst = smb + A_BYTES + (uint32_t)(bk*BS_PITCH + bn4)*4;

    int T = Kd >> 4;

    float acc[4][4][4];
    #pragma unroll
    for (int i=0;i<4;i++)
        #pragma unroll
        for (int j=0;j<4;j++)
            #pragma unroll
            for (int q=0;q<4;q++) acc[i][j][q]=0.f;

    auto issue = [&](int t){
        uint32_t so = (uint32_t)(t & 3) * STG_BYTES;
        int k0 = t << 4;
        cpa16(aDst + so, Arow + k0, asz);
        cpa16(bDst + so,                  Bp + (size_t)k0*ldb,     16);
        cpa16(bDst + so + BS_PITCH*8*4,   Bp + (size_t)(k0+8)*ldb, 16);
        CP_COMMIT();
    };

    #pragma unroll
    for (int s=0; s<NSTG-1; s++){
        if (s < T) issue(s); else CP_COMMIT();
    }

    int lrow = wm*64 + (lane & 15);
    uint32_t lbyte = (uint32_t)(lane >> 4) * 16;

    for (int t=0; t<T; t++){
        CP_WAIT2();
        __syncthreads();
        if (t + NSTG-1 < T) issue(t + NSTG-1); else CP_COMMIT();

        uint32_t Ab = smb + (uint32_t)(t&3)*STG_BYTES;
        const float* Bsf = (const float*)((const char*)dsmf + (size_t)(t&3)*STG_BYTES + A_BYTES);

        uint32_t a[4][4];
        #pragma unroll
        for (int i=0;i<4;i++){
            uint32_t ad = Ab + (uint32_t)((lrow + i*16)*AP16)*2 + lbyte;
            ldsm_x4(a[i], ad);
        }
        uint32_t b[4][2];
        #pragma unroll
        for (int j=0;j<4;j++){
            int col = wn*32 + j*8 + gq;
            __half2 h0 = __floats2half2_rn(Bsf[(2*lq)*BS_PITCH + col],
                                           Bsf[(2*lq+1)*BS_PITCH + col]);
            __half2 h1 = __floats2half2_rn(Bsf[(8+2*lq)*BS_PITCH + col],
                                           Bsf[(9+2*lq)*BS_PITCH + col]);
            b[j][0] = *(uint32_t*)&h0;
            b[j][1] = *(uint32_t*)&h1;
        }
        #pragma unroll
        for (int i=0;i<4;i++)
            #pragma unroll
            for (int j=0;j<4;j++)
                mma_f16(acc[i][j], a[i], b[j]);
    }

    #pragma unroll
    for (int i=0;i<4;i++){
        #pragma unroll
        for (int h=0;h<2;h++){
            int row = m0 + wm*64 + i*16 + gq + h*8;
            if (row < Mv){
                float* crow = Cc + (size_t)row*ldc;
                const float* rrow = res ? (res + (size_t)row*ldc) : nullptr;
                #pragma unroll
                for (int j=0;j<4;j++){
                    int cix = n0 + wn*32 + j*8 + lq*2;
                    float2 v = make_float2(acc[i][j][h*2], acc[i][j][h*2+1]);
                    if (rrow){
                        float2 rv = *(const float2*)(rrow + cix);
                        v.x += rv.x; v.y += rv.y;
                    }
                    *(float2*)(crow + cix) = v;
                }
            }
        }
    }
}

__global__ void __launch_bounds__(256,2)
k_tgemm(const __half* A, int lda, const float* B, int ldb,
        float* Cc, int ldc, const float* res, int Mv, int Kd){
    tgemm_core(A, lda, nullptr, B, ldb, Cc, ldc, res, Mv, Kd,
               blockIdx.y*128, blockIdx.x*128);
}

// z<E_: expert e ; z==E_: shared MLP
__global__ void __launch_bounds__(256,2)
k_tgemm_egu(const float* Wgu, const float* Wgu_s){
    int z = blockIdx.z, m0 = blockIdx.y*128;
    if (z < E_){
        int cnt = g_ecnt[z];
        if (m0 >= cnt) return;
        tgemm_core(g_x216, H_, &g_etok[z*C_], Wgu + (size_t)z*H_*2*I_, 2*I_,
                   &g_gu[(size_t)g_eoff[z]*2*I_], 2*I_, nullptr, cnt, H_,
                   m0, blockIdx.x*128);
    } else {
        tgemm_core(g_x216, H_, nullptr, Wgu_s, 2*I_,
                   g_gu_s, 2*I_, nullptr, S_, H_,
                   m0, blockIdx.x*128);
    }
}

__global__ void __launch_bounds__(256,2)
k_tgemm_edn(const float* Wd, const float* Wd_s){
    int z = blockIdx.z, m0 = blockIdx.y*128;
    if (z < E_){
        int cnt = g_ecnt[z];
        if (m0 >= cnt) return;
        int off = g_eoff[z];
        tgemm_core(&g_act16[(size_t)off*I_], I_, nullptr, Wd + (size_t)z*I_*H_, H_,
                   &g_ye[(size_t)off*H_], H_, nullptr, cnt, I_,
                   m0, blockIdx.x*128);
    } else {
        tgemm_core(g_act_s16, I_, nullptr, Wd_s, H_,
                   g_sh, H_, nullptr, S_, I_,
                   m0, blockIdx.x*128);
    }
}

// ---------------- elementwise / routing ----------------
__global__ void k_rmsnorm(const float* __restrict__ x, const float* __restrict__ w,
                          __half* __restrict__ y16, float* __restrict__ yf){
    int row = blockIdx.x, tid = threadIdx.x;
    float4 xv = ((const float4*)(x + (size_t)row*H_))[tid];
    float ss = xv.x*xv.x + xv.y*xv.y + xv.z*xv.z + xv.w*xv.w;
    #pragma unroll
    for (int m=16;m;m>>=1) ss += __shfl_xor_sync(0xffffffffu, ss, m);
    __shared__ float wsum[8];
    if ((tid&31)==0) wsum[tid>>5]=ss;
    __syncthreads();
    if (tid<8){
        float v=wsum[tid];
        #pragma unroll
        for (int m=4;m;m>>=1) v+=__shfl_xor_sync(0xffu,v,m);
        if (tid==0) wsum[0]=v;
    }
    __syncthreads();
    float inv = rsqrtf(wsum[0]*(1.0f/H_) + 1e-6f);
    float4 wv = ((const float4*)w)[tid];
    float4 o = make_float4(wv.x*xv.x*inv, wv.y*xv.y*inv, wv.z*xv.z*inv, wv.w*xv.w*inv);
    __half2* y2 = (__half2*)(y16 + (size_t)row*H_);
    y2[tid*2]   = __floats2half2_rn(o.x, o.y);
    y2[tid*2+1] = __floats2half2_rn(o.z, o.w);
    if (yf) ((float4*)(yf + (size_t)row*H_))[tid] = o;
}

__global__ void k_rope(const float* __restrict__ qkv, const float* __restrict__ cb,
                       const float* __restrict__ sb, const float* __restrict__ qw,
                       const float* __restrict__ kw){
    int s = blockIdx.x, y = blockIdx.y, lane = threadIdx.x;
    const float* base; float* outp; const float* w;
    if (y < NH_){
        int kvh = y>>1, g = y&1;
        base = qkv + (size_t)s*2048 + kvh*256 + g*64;
        outp = &g_q[((size_t)y*S_ + s)*HD_];
        w = qw;
    } else {
        int kvh = y - NH_;
        base = qkv + (size_t)s*2048 + kvh*256 + 128;
        outp = &g_k[((size_t)kvh*S_ + s)*HD_];
        w = kw;
        float* vo = &g_v[((size_t)kvh*S_ + s)*HD_];
        vo[lane] = base[64+lane]; vo[lane+32] = base[96+lane];
    }
    float x0 = base[lane], x1 = base[lane+32];
    float r0 = x0*cb[s*HD_+lane]    - x1*sb[s*HD_+lane];
    float r1 = x1*cb[s*HD_+32+lane] + x0*sb[s*HD_+32+lane];
    float ss = r0*r0 + r1*r1;
    #pragma unroll
    for (int m=16;m;m>>=1) ss += __shfl_xor_sync(0xffffffffu, ss, m);
    float inv = rsqrtf(ss*(1.f/HD_) + 1e-6f);
    outp[lane] = w[lane]*r0*inv;
    outp[lane+32] = w[lane+32]*r1*inv;
}

// ---------------- attention: BQ=16, BK=32, heavy-first, fp16 output ----------------
__global__ void k_attn(const float* __restrict__ Q, const float* __restrict__ Kg,
                       const float* __restrict__ Vg, __half* __restrict__ out){
    const int BQ=16, BK=32;
    int qt = (int)gridDim.x - 1 - (int)blockIdx.x;
    int h = blockIdx.y, kvh = h>>1;
    const float* Qh = Q + ((size_t)h*S_ + qt*BQ)*HD_;
    const float* Kh = Kg + (size_t)kvh*S_*HD_;
    const float* Vh = Vg + (size_t)kvh*S_*HD_;
    __shared__ __align__(16) float Qs[16][68];
    __shared__ __align__(16) float Ks[32][68];
    __shared__ __align__(16) float Vs[32][68];
    __shared__ float Ps[16][33];
    int tid = threadIdx.x;
    int r = tid>>4, cg = tid&15;
    {
        int row = tid>>4, d4 = tid&15;
        *(float4*)&Qs[row][d4*4] = ((const float4*)(Qh + row*HD_))[d4];
    }
    float o[4] = {0.f,0.f,0.f,0.f};
    float mrow=-1e30f, lrow=0.f;
    int ntiles = (qt+2)>>1;
    int qg = qt*BQ + r;
    __syncthreads();
    for (int kt=0; kt<ntiles; kt++){
        __syncthreads();
        for (int idx=tid; idx<BK*16; idx+=256){
            int row = idx>>4, d4 = idx&15;
            *(float4*)&Ks[row][d4*4] = ((const float4*)(Kh + (kt*BK+row)*HD_))[d4];
            *(float4*)&Vs[row][d4*4] = ((const float4*)(Vh + (kt*BK+row)*HD_))[d4];
        }
        __syncthreads();
        float sc[2]; sc[0]=0.f; sc[1]=0.f;
        #pragma unroll
        for (int d4=0; d4<16; d4++){
            float4 qv = *(const float4*)&Qs[r][d4*4];
            #pragma unroll
            for (int j=0;j<2;j++){
                float4 kv = *(const float4*)&Ks[cg+16*j][d4*4];
                sc[j] += qv.x*kv.x + qv.y*kv.y + qv.z*kv.z + qv.w*kv.w;
            }
        }
        float tmax=-1e30f;
        #pragma unroll
        for (int j=0;j<2;j++){
            int kgl = kt*BK + cg + 16*j;
            sc[j] = (kgl<=qg) ? sc[j]*0.125f : -1e30f;
            tmax = fmaxf(tmax, sc[j]);
        }
        #pragma unroll
        for (int m=1;m<16;m<<=1) tmax = fmaxf(tmax, __shfl_xor_sync(0xffffffffu, tmax, m));
        float mnew = fmaxf(mrow, tmax);
        float fac = expf(mrow - mnew);
        float ps=0.f;
        #pragma unroll
        for (int j=0;j<2;j++){
            float p = expf(sc[j]-mnew);
            Ps[r][cg+16*j] = p;
            ps += p;
        }
        #pragma unroll
        for (int m=1;m<16;m<<=1) ps += __shfl_xor_sync(0xffffffffu, ps, m);
        lrow = lrow*fac + ps;
        mrow = mnew;
        o[0]*=fac; o[1]*=fac; o[2]*=fac; o[3]*=fac;
        __syncwarp();
        #pragma unroll 8
        for (int k=0;k<BK;k++){
            float p = Ps[r][k];
            float4 v = *(const float4*)&Vs[k][cg*4];
            o[0]+=p*v.x; o[1]+=p*v.y; o[2]+=p*v.z; o[3]+=p*v.w;
        }
    }
    float inv = 1.f/lrow;
    __half2* orow = (__half2*)(out + (size_t)(qt*BQ+r)*H_ + h*HD_ + cg*4);
    orow[0] = __floats2half2_rn(o[0]*inv, o[1]*inv);
    orow[1] = __floats2half2_rn(o[2]*inv, o[3]*inv);
}

// fused swiglu over expert rows then shared rows; fp16 outputs
__global__ void k_swiglu(){
    int rows_e = g_eoff[E_];
    const int HC = I_/2;
    long long total = (long long)(rows_e + S_) * HC;
    for (long long idx = blockIdx.x*(long long)blockDim.x + threadIdx.x;
         idx < total; idx += (long long)gridDim.x*blockDim.x){
        int rr = (int)(idx / HC), c2 = (int)(idx % HC) * 2;
        if (rr < rows_e){
            const float* g = &g_gu[(size_t)rr*(2*I_)];
            float a0 = g[c2],   b0 = g[I_+c2];
            float a1 = g[c2+1], b1 = g[I_+c2+1];
            float v0 = a0 * (b0 / (1.f + expf(-b0)));
            float v1 = a1 * (b1 / (1.f + expf(-b1)));
            *(__half2*)&g_act16[(size_t)rr*I_ + c2] = __floats2half2_rn(v0, v1);
        } else {
            int rs = rr - rows_e;
            const float* g = &g_gu_s[(size_t)rs*(2*I_)];
            float a0 = g[c2],   b0 = g[I_+c2];
            float a1 = g[c2+1], b1 = g[I_+c2+1];
            float v0 = a0 * (b0 / (1.f + expf(-b0)));
            float v1 = a1 * (b1 / (1.f + expf(-b1)));
            *(__half2*)&g_act_s16[(size_t)rs*I_ + c2] = __floats2half2_rn(v0, v1);
        }
    }
}

__global__ void k_gate(const float* __restrict__ x2, const float* __restrict__ Wg){
    __shared__ float row[H_];
    int t = blockIdx.x, tid = threadIdx.x;
    for (int i=tid;i<H_/4;i+=64) ((float4*)row)[i] = ((const float4*)(x2+(size_t)t*H_))[i];
    __syncthreads();
    float acc=0.f;
    #pragma unroll 4
    for (int h=0;h<H_;h++) acc += row[h]*Wg[h*E_+tid];
    g_lg[t*E_+tid]=acc;
}

__global__ void k_topk(){
    int t = blockIdx.x, lane = threadIdx.x;
    float v0 = g_lg[t*E_+lane], v1 = g_lg[t*E_+32+lane];
    float topv[TK_]; int topi[TK_];
    #pragma unroll
    for (int k=0;k<TK_;k++){
        float bv; int bi;
        if (v0 >= v1){ bv=v0; bi=lane; } else { bv=v1; bi=lane+32; }
        #pragma unroll
        for (int m=16;m;m>>=1){
            float ov = __shfl_xor_sync(0xffffffffu, bv, m);
            int   oi = __shfl_xor_sync(0xffffffffu, bi, m);
            if (ov > bv || (ov==bv && oi<bi)){ bv=ov; bi=oi; }
        }
        topv[k]=bv; topi[k]=bi;
        if (bi==lane)    v0=-3.0e38f;
        if (bi==lane+32) v1=-3.0e38f;
    }
    if (lane==0){
        float m0 = topv[0], s=0.f, ex[TK_];
        #pragma unroll
        for (int k=0;k<TK_;k++){ ex[k]=expf(topv[k]-m0); s+=ex[k]; }
        float invs = 1.f/s;
        #pragma unroll
        for (int k=0;k<TK_;k++){ g_w8[t*TK_+k]=ex[k]*invs; g_idx8[t*TK_+k]=topi[k]; }
    }
}

__global__ void k_route(){
    int e = blockIdx.x, tid = threadIdx.x;
    __shared__ int sc[256];
    const int per = MAXPAIRS_/256;
    int base = tid*per, c=0;
    for (int j=0;j<per;j++) if (g_idx8[base+j]==e) c++;
    sc[tid]=c; __syncthreads();
    for (int off=1; off<256; off<<=1){
        int v = (tid>=off)? sc[tid-off] : 0;
        __syncthreads();
        sc[tid] += v;
        __syncthreads();
    }
    int p = sc[tid]-c;
    for (int j=0;j<per;j++){
        int i = base+j;
        if (g_idx8[i]==e){
            if (p < C_){ g_etok[e*C_+p] = i>>3; g_ppos[i]=p; }
            else g_ppos[i] = -1;
            p++;
        }
    }
    if (tid==255) g_ecnt[e] = min(sc[255], C_);
}

__global__ void k_offsets(){
    if (threadIdx.x==0){
        int s=0;
        for (int e=0;e<E_;e++){ g_eoff[e]=s; s+=g_ecnt[e]; }
        g_eoff[E_]=s;
    }
}

__global__ void k_combine(const float* __restrict__ h1, const float* __restrict__ sh,
                          float* __restrict__ out){
    int t = blockIdx.x, tid = threadIdx.x;
    size_t base = (size_t)t*H_ + tid*4;
    float4 a = *(const float4*)(h1+base);
    float4 b = *(const float4*)(sh+base);
    a.x+=b.x; a.y+=b.y; a.z+=b.z; a.w+=b.w;
    #pragma unroll
    for (int k=0;k<TK_;k++){
        int p = g_ppos[t*TK_+k];
        if (p>=0){
            int e = g_idx8[t*TK_+k];
            float w = g_w8[t*TK_+k];
            float4 y = ((const float4*)&g_ye[(size_t)(g_eoff[e]+p)*H_])[tid];
            a.x += w*y.x; a.y += w*y.y; a.z += w*y.z; a.w += w*y.w;
        }
    }
    *(float4*)(out+base) = a;
}

// ---------------- launch ----------------
extern "C" void kernel_launch(void* const* d_in, const int* in_sizes, int n_in,
                              void* d_out, int out_size){
    const float* hs    = (const float*)d_in[0];
    const float* cb    = (const float*)d_in[1];
    const float* sb    = (const float*)d_in[2];
    const float* ln1   = (const float*)d_in[3];
    const float* ln2   = (const float*)d_in[4];
    const float* Wqkv  = (const float*)d_in[5];
    const float* Wo    = (const float*)d_in[6];
    const float* qw    = (const float*)d_in[7];
    const float* kw    = (const float*)d_in[8];
    const float* Wgu_s = (const float*)d_in[9];
    const float* Wd_s  = (const float*)d_in[10];
    const float* Wgate = (const float*)d_in[11];
    const float* Wgu_e = (const float*)d_in[12];
    const float* Wd_e  = (const float*)d_in[13];
    float* out = (float*)d_out;

    __half *p_xln16, *p_attn16, *p_x216;
    float *p_qkv,*p_q,*p_k,*p_v,*p_h1,*p_x2,*p_sh;
    cudaGetSymbolAddress((void**)&p_xln16,  g_xln16);
    cudaGetSymbolAddress((void**)&p_qkv,    g_qkv);
    cudaGetSymbolAddress((void**)&p_q,      g_q);
    cudaGetSymbolAddress((void**)&p_k,      g_k);
    cudaGetSymbolAddress((void**)&p_v,      g_v);
    cudaGetSymbolAddress((void**)&p_attn16, g_attn16);
    cudaGetSymbolAddress((void**)&p_h1,     g_h1);
    cudaGetSymbolAddress((void**)&p_x2,     g_x2);
    cudaGetSymbolAddress((void**)&p_x216,   g_x216);
    cudaGetSymbolAddress((void**)&p_sh,     g_sh);

    cudaFuncSetAttribute(k_tgemm,     cudaFuncAttributeMaxDynamicSharedMemorySize, SMEM_BYTES);
    cudaFuncSetAttribute(k_tgemm_egu, cudaFuncAttributeMaxDynamicSharedMemorySize, SMEM_BYTES);
    cudaFuncSetAttribute(k_tgemm_edn, cudaFuncAttributeMaxDynamicSharedMemorySize, SMEM_BYTES);

    k_rmsnorm<<<S_,256>>>(hs, ln1, p_xln16, nullptr);
    k_tgemm<<<dim3(2048/128, 8),256,SMEM_BYTES>>>(p_xln16, H_, Wqkv, 2048, p_qkv, 2048, nullptr, S_, H_);
    k_rope<<<dim3(S_, NH_+KVH_),32>>>(p_qkv, cb, sb, qw, kw);
    k_attn<<<dim3(S_/16, NH_),256>>>(p_q, p_k, p_v, p_attn16);
    k_tgemm<<<dim3(H_/128, 8),256,SMEM_BYTES>>>(p_attn16, H_, Wo, H_, p_h1, H_, hs, S_, H_);
    k_rmsnorm<<<S_,256>>>(p_h1, ln2, p_x216, p_x2);
    // routing
    k_gate<<<S_,64>>>(p_x2, Wgate);
    k_topk<<<S_,32>>>();
    k_route<<<E_,256>>>();
    k_offsets<<<1,32>>>();
    // fused expert + shared-MLP GEMMs (fp16 tensor path)
    k_tgemm_egu<<<dim3((2*I_)/128, 8, E_+1),256,SMEM_BYTES>>>(Wgu_e, Wgu_s);
    k_swiglu<<<6144,256>>>();
    k_tgemm_edn<<<dim3(H_/128, 8, E_+1),256,SMEM_BYTES>>>(Wd_e, Wd_s);
    k_combine<<<S_,256>>>(p_h1, p_sh, out);
}